// round 10
// baseline (speedup 1.0000x reference)
#include <cuda_runtime.h>
#include <cuda_bf16.h>
#include <math.h>

#define RTOT 69632
#define HOFF 65536
typedef unsigned long long ull;

__device__ __forceinline__ ull pk2(float a, float b) {
    ull r; asm("mov.b64 %0,{%1,%2};" : "=l"(r) : "f"(a), "f"(b)); return r;
}
__device__ __forceinline__ ull ff2(ull a, ull b, ull c) {
    ull d; asm("fma.rn.f32x2 %0,%1,%2,%3;" : "=l"(d) : "l"(a), "l"(b), "l"(c)); return d;
}
__device__ __forceinline__ ull ml2(ull a, ull b) {
    ull d; asm("mul.rn.f32x2 %0,%1,%2;" : "=l"(d) : "l"(a), "l"(b)); return d;
}
__device__ __forceinline__ float2 up2(ull v) {
    float2 f; asm("mov.b64 {%0,%1},%2;" : "=f"(f.x), "=f"(f.y) : "l"(v)); return f;
}

// ---------------- scratch ----------------
__device__ float g_tokA[RTOT*64];
__device__ float g_tokB[RTOT*64];
__device__ float g_xz  [RTOT*256];
__device__ float g_u   [RTOT*128];
__device__ float g_dt  [RTOT*128];
__device__ float g_bc  [RTOT*32];
__device__ float g_hend [1088*2048];
__device__ float g_hinit[1088*2048];
__device__ float g_sdt  [1088*128];
__device__ float g_featT[4096*64];
__device__ float g_guideT[65536*64];
__device__ float g_F1[4096*256];
__device__ float g_G1[65536*256];
__device__ float g_WinT[4*16384];
__device__ float g_WoutT[4*8192];
__device__ float g_W1fT[16384];
__device__ float g_W1gT[16384];
__device__ float g_Wr[512];
__device__ float g_W2T[32768];
__device__ float g_WxpP[4*4752];
__device__ float g_WdtT[4*512];
__device__ float g_cwT[4*512];

// ---------------- one-shot weight prep ----------------
__global__ void k_prep(const float* __restrict__ Win, const float* __restrict__ Wout,
                       const float* __restrict__ W1, const float* __restrict__ W2,
                       const float* __restrict__ Wxp, const float* __restrict__ Wdt,
                       const float* __restrict__ convw,
                       float* WinT, float* WoutT, float* W1fT, float* W1gT, float* Wr,
                       float* W2T, float* WxpP, float* WdtT, float* cwT) {
    int i = blockIdx.x*256 + threadIdx.x;
    if (i < 65536) { int blk=i>>14, r=i&16383, k=r>>8, o=r&255; WinT[i]=Win[blk*16384+o*64+k]; return; }
    i -= 65536;
    if (i < 32768) { int blk=i>>13, r=i&8191, k=r>>6, o=r&63; WoutT[i]=Wout[blk*8192+o*128+k]; return; }
    i -= 32768;
    if (i < 16384) { int k=i>>8, o=i&255; W1fT[i]=W1[o*130+k]; return; }
    i -= 16384;
    if (i < 16384) { int k=i>>8, o=i&255; W1gT[i]=W1[o*130+64+k]; return; }
    i -= 16384;
    if (i < 512)   { Wr[i]=W1[(i>>1)*130+128+(i&1)]; return; }
    i -= 512;
    if (i < 32768) { int k=i>>7, j=i&127; W2T[i]=W2[j*256+k]; return; }
    i -= 32768;
    if (i < 18432) { int blk=i/4608, r=i%4608; WxpP[blk*4752 + (r>>7)*132 + (r&127)] = Wxp[i]; return; }
    i -= 18432;
    if (i < 2048)  { int blk=i>>9, rr=i&511, r=rr>>7, d=rr&127; WdtT[i]=Wdt[blk*512+d*4+r]; return; }
    i -= 2048;
    if (i < 2048)  { int blk=i>>9, rr=i&511, j=rr>>7, d=rr&127; cwT[i]=convw[blk*512+d*4+j]; return; }
}

// ---------------- merged encoder conv ----------------
__global__ void k_conv(const float* __restrict__ msi, const float* __restrict__ hsi,
                       const float* __restrict__ emw, const float* __restrict__ emb,
                       const float* __restrict__ ehw, const float* __restrict__ ehb,
                       float* __restrict__ outp) {
    if (blockIdx.x < 16384) {
        int idx = blockIdx.x*256 + threadIdx.x;
        int x = idx & 127, y = (idx >> 7) & 127, co = (idx >> 14) & 63, b = idx >> 20;
        float acc = emb[co];
        #pragma unroll
        for (int ci = 0; ci < 4; ci++)
            #pragma unroll
            for (int ky = 0; ky < 3; ky++) {
                int yy = y + ky - 1; if (yy < 0 || yy >= 128) continue;
                #pragma unroll
                for (int kx = 0; kx < 3; kx++) {
                    int xx = x + kx - 1; if (xx < 0 || xx >= 128) continue;
                    acc += emw[((co*4 + ci)*3 + ky)*3 + kx] * msi[((b*4 + ci)*128 + yy)*128 + xx];
                }
            }
        outp[idx] = fmaxf(acc, 0.f);
    } else {
        int idx = (blockIdx.x - 16384)*256 + threadIdx.x;
        int x = idx & 31, y = (idx >> 5) & 31, co = (idx >> 10) & 63, b = idx >> 16;
        float acc = ehb[co];
        for (int ci = 0; ci < 31; ci++)
            #pragma unroll
            for (int ky = 0; ky < 3; ky++) {
                int yy = y + ky - 1; if (yy < 0 || yy >= 32) continue;
                #pragma unroll
                for (int kx = 0; kx < 3; kx++) {
                    int xx = x + kx - 1; if (xx < 0 || xx >= 32) continue;
                    acc += ehw[((co*31 + ci)*3 + ky)*3 + kx] * hsi[((b*31 + ci)*32 + yy)*32 + xx];
                }
            }
        outp[HOFF*64 + idx] = fmaxf(acc, 0.f);
    }
}

// ---------------- merged matmul (f32x2) ----------------
template<int IN, int OUT, int RT>
__global__ void k_mmT(const float* __restrict__ Xm, const float* __restrict__ Xh,
                      const float* __restrict__ Wm, const float* __restrict__ Wh,
                      const float* __restrict__ bm, const float* __restrict__ bh,
                      float* __restrict__ Ym, float* __restrict__ Yh, int HB) {
    constexpr int nOG = OUT/4;
    constexpr int RB  = RT*(256/nOG);
    extern __shared__ float sm[];
    float* Ws = sm;
    float* Xs = sm + IN*OUT;
    int tid = threadIdx.x;
    const float *X, *WT, *bias; float* Y; size_t row0;
    if ((int)blockIdx.x < HB) { X=Xm; WT=Wm; bias=bm; Y=Ym; row0=(size_t)blockIdx.x*RB; }
    else { X=Xh; WT=Wh; bias=bh; Y=Yh; row0=(size_t)(blockIdx.x-HB)*RB; }
    for (int i = tid; i < OUT*IN/4; i += 256) ((float4*)Ws)[i] = ((const float4*)WT)[i];
    for (int i = tid; i < RB*IN/4; i += 256)
        ((float4*)Xs)[i] = ((const float4*)(X + row0*IN))[i];
    __syncthreads();
    int og = tid % nOG, rg = tid / nOG;
    float4 bv = bias ? *(const float4*)(bias + og*4) : make_float4(0.f,0.f,0.f,0.f);
    ull acc2[RT][2];
    #pragma unroll
    for (int r = 0; r < RT; r++) { acc2[r][0] = pk2(bv.x, bv.y); acc2[r][1] = pk2(bv.z, bv.w); }
    #pragma unroll 2
    for (int k = 0; k < IN; k += 4) {
        ulonglong2 w0 = *(const ulonglong2*)&Ws[(k+0)*OUT + og*4];
        ulonglong2 w1 = *(const ulonglong2*)&Ws[(k+1)*OUT + og*4];
        ulonglong2 w2 = *(const ulonglong2*)&Ws[(k+2)*OUT + og*4];
        ulonglong2 w3 = *(const ulonglong2*)&Ws[(k+3)*OUT + og*4];
        #pragma unroll
        for (int r = 0; r < RT; r++) {
            float4 av = *(const float4*)&Xs[(rg*RT + r)*IN + k];
            ull ax = pk2(av.x, av.x), ay = pk2(av.y, av.y);
            ull az = pk2(av.z, av.z), aw = pk2(av.w, av.w);
            acc2[r][0] = ff2(w0.x, ax, acc2[r][0]); acc2[r][1] = ff2(w0.y, ax, acc2[r][1]);
            acc2[r][0] = ff2(w1.x, ay, acc2[r][0]); acc2[r][1] = ff2(w1.y, ay, acc2[r][1]);
            acc2[r][0] = ff2(w2.x, az, acc2[r][0]); acc2[r][1] = ff2(w2.y, az, acc2[r][1]);
            acc2[r][0] = ff2(w3.x, aw, acc2[r][0]); acc2[r][1] = ff2(w3.y, aw, acc2[r][1]);
        }
    }
    #pragma unroll
    for (int r = 0; r < RT; r++) {
        float2 lo = up2(acc2[r][0]), hi = up2(acc2[r][1]);
        float4 o; o.x = lo.x; o.y = lo.y; o.z = hi.x; o.w = hi.y;
        *(float4*)&Y[(row0 + rg*RT + r)*OUT + og*4] = o;
    }
}

// ---------------- fused convproj + scan pass1 (64 tokens = 1 chunk / block) ----------------
// smem floats: WXPS 0(4752) US 4752(8448,str132) DTS 13200(8192) XDS 21392(2560)
//              WDT 23952(512) BDT 24464(128) CW 24592(512) CB 25104(128)  TOT 25232
#define CP_TOT 25232
__device__ __forceinline__ bool load_A(const float* Alog, int d, float* An) {
    #pragma unroll
    for (int n = 0; n < 16; n++) An[n] = -__expf(Alog[d*16 + n]);
    bool geom = true;
    #pragma unroll
    for (int n = 1; n < 16; n++)
        if (fabsf(An[n] - (float)(n+1)*An[0]) > 1e-4f*(float)(n+1)) geom = false;
    return geom;
}

__global__ void k_cps1(const float* __restrict__ xz, const float* __restrict__ cwT,
        const float* __restrict__ convb, const float* __restrict__ WxpP,
        const float* __restrict__ WdtT, const float* __restrict__ bdt,
        const float* __restrict__ Alog,
        float* __restrict__ u_out, float* __restrict__ dt_out, float* __restrict__ bc_out,
        float* __restrict__ hend, float* __restrict__ sdt_out, int blkM, int blkH) {
    extern __shared__ float sm[];
    float* WXPS = sm;
    float* US   = sm + 4752;
    float* DTS  = sm + 13200;
    float* XDS  = sm + 21392;
    float* WDT  = sm + 23952;
    float* BDT  = sm + 24464;
    float* CW   = sm + 24592;
    float* CB   = sm + 25104;
    int tid = threadIdx.x;
    int chunk = blockIdx.x;
    int blk, Lmask;
    if (chunk < 1024) { blk = blkM; Lmask = 16383; } else { blk = blkH; Lmask = 1023; }
    size_t g0 = (size_t)chunk*64;
    for (int i = tid; i < 4752; i += 256) WXPS[i] = WxpP[blk*4752 + i];
    for (int i = tid; i < 512; i += 256) { WDT[i] = WdtT[blk*512 + i]; CW[i] = cwT[blk*512 + i]; }
    if (tid < 128) { BDT[tid] = bdt[blk*128 + tid]; CB[tid] = convb[blk*128 + tid]; }
    __syncthreads();
    // phase 1: depthwise conv + silu
    for (int i = tid; i < 2048; i += 256) {
        int tt = i >> 5, d4 = (i & 31)*4;
        size_t g = g0 + tt;
        int t = (int)(g & Lmask);
        float4 acc = *(const float4*)&CB[d4];
        #pragma unroll
        for (int j = 0; j < 4; j++) {
            if (t - 3 + j >= 0) {
                float4 xv = *(const float4*)&xz[(g-3+j)*256 + d4];
                float4 wv = *(const float4*)&CW[j*128 + d4];
                acc.x += wv.x*xv.x; acc.y += wv.y*xv.y; acc.z += wv.z*xv.z; acc.w += wv.w*xv.w;
            }
        }
        float4 uu;
        uu.x = acc.x/(1.f+__expf(-acc.x)); uu.y = acc.y/(1.f+__expf(-acc.y));
        uu.z = acc.z/(1.f+__expf(-acc.z)); uu.w = acc.w/(1.f+__expf(-acc.w));
        *(float4*)&US[tt*132 + d4] = uu;
        *(float4*)&u_out[g*128 + d4] = uu;
    }
    __syncthreads();
    // phase 2: xdbl = u @ Wxp^T (36 outs), o-pairs, tt-fast lanes
    for (int i = tid; i < 1152; i += 256) {
        int tt = i & 63, op = i >> 6;
        int o0 = op*2;
        const float* up = &US[tt*132];
        const float* w0p = &WXPS[o0*132];
        const float* w1p = &WXPS[o0*132 + 132];
        float a0 = 0.f, a1 = 0.f;
        #pragma unroll 4
        for (int k = 0; k < 128; k += 4) {
            float4 uv = *(const float4*)&up[k];
            float4 w0 = *(const float4*)&w0p[k];
            float4 w1 = *(const float4*)&w1p[k];
            a0 += w0.x*uv.x + w0.y*uv.y + w0.z*uv.z + w0.w*uv.w;
            a1 += w1.x*uv.x + w1.y*uv.y + w1.z*uv.z + w1.w*uv.w;
        }
        XDS[tt*40 + o0] = a0; XDS[tt*40 + o0 + 1] = a1;
    }
    __syncthreads();
    // phase 3: bc out + dt
    for (int i = tid; i < 2048; i += 256) {
        int tt = i >> 5, c = i & 31;
        bc_out[(g0+tt)*32 + c] = XDS[tt*40 + 4 + c];
    }
    for (int i = tid; i < 2048; i += 256) {
        int tt = i >> 5, d4 = (i & 31)*4;
        float4 dtp = *(const float4*)&BDT[d4];
        #pragma unroll
        for (int r = 0; r < 4; r++) {
            float x = XDS[tt*40 + r];
            float4 wv = *(const float4*)&WDT[r*128 + d4];
            dtp.x += x*wv.x; dtp.y += x*wv.y; dtp.z += x*wv.z; dtp.w += x*wv.w;
        }
        float4 o;
        o.x = (dtp.x > 20.f) ? dtp.x : log1pf(__expf(dtp.x));
        o.y = (dtp.y > 20.f) ? dtp.y : log1pf(__expf(dtp.y));
        o.z = (dtp.z > 20.f) ? dtp.z : log1pf(__expf(dtp.z));
        o.w = (dtp.w > 20.f) ? dtp.w : log1pf(__expf(dtp.w));
        *(float4*)&DTS[tt*128 + d4] = o;
        *(float4*)&dt_out[(g0+tt)*128 + d4] = o;
    }
    __syncthreads();
    // phase 4: scan pass 1 (h0 = 0)
    if (tid < 128) {
        int d = tid;
        float An[16];
        bool geom = load_A(Alog + blk*2048, d, An);
        float h[16];
        #pragma unroll
        for (int n = 0; n < 16; n++) h[n] = 0.f;
        float s = 0.f;
        for (int tt = 0; tt < 64; tt++) {
            float dtv = DTS[tt*128 + d];
            float du = dtv * US[tt*132 + d];
            s += dtv;
            const float* Bv = &XDS[tt*40 + 4];
            if (geom) {
                float ep[16];
                ep[0] = __expf(dtv * An[0]);
                #pragma unroll
                for (int n = 1; n < 16; n++) ep[n] = ep[(n-1)>>1]*ep[n>>1];
                #pragma unroll
                for (int n = 0; n < 16; n++) h[n] = ep[n]*h[n] + du*Bv[n];
            } else {
                #pragma unroll
                for (int n = 0; n < 16; n++) h[n] = __expf(dtv*An[n])*h[n] + du*Bv[n];
            }
        }
        float* he = hend + ((size_t)chunk*128 + d)*16;
        #pragma unroll
        for (int n = 0; n < 16; n++) he[n] = h[n];
        sdt_out[chunk*128 + d] = s;
    }
}

// ---------------- carry (MLP=8 prefetch) ----------------
__global__ void k_carry(const float* __restrict__ hend, const float* __restrict__ sdt,
                        const float* __restrict__ Alog, float* __restrict__ hinit,
                        int blkM, int blkH) {
    int blk = blockIdx.x;
    int tid = threadIdx.x;
    int NC, chunk0, half; const float* Al;
    if (blk < 8) { NC = 256; chunk0 = (blk >> 1)*256; half = blk & 1; Al = Alog + blkM*2048; }
    else { int i = blk - 8; NC = 16; chunk0 = 1024 + (i >> 1)*16; half = i & 1; Al = Alog + blkH*2048; }
    int d = half*64 + (tid >> 4), n = tid & 15;
    float An = -__expf(Al[d*16 + n]);
    float h = 0.f;
    for (int c0 = 0; c0 < NC; c0 += 8) {
        float e8[8], v8[8];
        #pragma unroll
        for (int j = 0; j < 8; j++) {
            size_t off = (size_t)(chunk0 + c0 + j)*2048 + half*1024 + tid;
            v8[j] = hend[off];
            e8[j] = __expf(sdt[(chunk0 + c0 + j)*128 + d]*An);
        }
        #pragma unroll
        for (int j = 0; j < 8; j++) {
            size_t off = (size_t)(chunk0 + c0 + j)*2048 + half*1024 + tid;
            hinit[off] = h;
            h = e8[j]*h + v8[j];
        }
    }
}

// ---------------- fused scan pass2 + output matmul ----------------
// smem floats: DT 0(8192) UU 8192(8192) BC 16384(2048) ZS 18432(8192) WO 26624(8192) YZ 34816(8192)
#define S2_TOT 43008
__global__ void k_s2mm(const float* __restrict__ dt_a, const float* __restrict__ u_a,
                       const float* __restrict__ bc_a, const float* __restrict__ Alog,
                       const float* __restrict__ hinit, const float* __restrict__ xz,
                       const float* __restrict__ Dp, const float* __restrict__ WoutT,
                       float* __restrict__ dst, int blkM, int blkH) {
    extern __shared__ float sm[];
    float* dtS = sm;
    float* uS  = sm + 8192;
    float* bcS = sm + 16384;
    float* zS  = sm + 18432;
    float* wS  = sm + 26624;
    float* yzs = sm + 34816;
    int tid = threadIdx.x;
    int chunk = blockIdx.x;
    int blk = (chunk < 1024) ? blkM : blkH;
    size_t g0 = (size_t)chunk*64;
    const float4* dg = (const float4*)(dt_a + g0*128);
    const float4* ug = (const float4*)(u_a + g0*128);
    const float4* bg = (const float4*)(bc_a + g0*32);
    const float4* wg = (const float4*)(WoutT + blk*8192);
    for (int i = tid; i < 2048; i += 256) { ((float4*)dtS)[i] = dg[i]; ((float4*)uS)[i] = ug[i]; }
    for (int i = tid; i < 512;  i += 256) ((float4*)bcS)[i] = bg[i];
    for (int i = tid; i < 2048; i += 256) {
        int tt = i >> 5, c4 = (i & 31)*4;
        *(float4*)&zS[tt*128 + c4] = *(const float4*)&xz[(g0+tt)*256 + 128 + c4];
    }
    for (int i = tid; i < 2048; i += 256) ((float4*)wS)[i] = wg[i];
    __syncthreads();
    if (tid < 128) {
        int d = tid;
        float An[16];
        bool geom = load_A(Alog + blk*2048, d, An);
        ull h2[8];
        const float* hi = hinit + ((size_t)chunk*128 + d)*16;
        #pragma unroll
        for (int j = 0; j < 8; j++) h2[j] = *(const ull*)&hi[2*j];
        float dcoef = Dp[blk*128 + d];
        for (int tt = 0; tt < 64; tt++) {
            float dtv = dtS[tt*128 + d];
            float u = uS[tt*128 + d];
            float du = dtv * u;
            ull du2 = pk2(du, du);
            ull ep2[8];
            if (geom) {
                float e1 = __expf(dtv * An[0]);
                float e2 = e1*e1;
                ep2[0] = pk2(e1, e2);
                ull f2 = pk2(e2, e2);
                #pragma unroll
                for (int j = 1; j < 8; j++) ep2[j] = ml2(ep2[j-1], f2);
            } else {
                #pragma unroll
                for (int j = 0; j < 8; j++)
                    ep2[j] = pk2(__expf(dtv*An[2*j]), __expf(dtv*An[2*j+1]));
            }
            ull y2 = pk2(0.f, 0.f);
            const float* Bv = &bcS[tt*32];
            #pragma unroll
            for (int j = 0; j < 8; j++) {
                ull b2 = *(const ull*)&Bv[2*j];
                ull c2 = *(const ull*)&Bv[16 + 2*j];
                h2[j] = ff2(ep2[j], h2[j], ml2(du2, b2));
                y2 = ff2(h2[j], c2, y2);
            }
            float2 yp = up2(y2);
            float ys = yp.x + yp.y + u*dcoef;
            float z = zS[tt*128 + d];
            yzs[tt*128 + d] = ys * (z/(1.f+__expf(-z)));
        }
    }
    __syncthreads();
    // output matmul: 64 tokens x 64 outs, IN=128
    int og = tid & 15, rg = tid >> 4;     // 16 row-groups x 4 rows
    ull acc2[4][2];
    #pragma unroll
    for (int r = 0; r < 4; r++) { acc2[r][0] = pk2(0.f, 0.f); acc2[r][1] = pk2(0.f, 0.f); }
    #pragma unroll 2
    for (int k = 0; k < 128; k += 4) {
        ulonglong2 w0 = *(const ulonglong2*)&wS[(k+0)*64 + og*4];
        ulonglong2 w1 = *(const ulonglong2*)&wS[(k+1)*64 + og*4];
        ulonglong2 w2 = *(const ulonglong2*)&wS[(k+2)*64 + og*4];
        ulonglong2 w3 = *(const ulonglong2*)&wS[(k+3)*64 + og*4];
        #pragma unroll
        for (int r = 0; r < 4; r++) {
            float4 av = *(const float4*)&yzs[(rg*4 + r)*128 + k];
            ull ax = pk2(av.x, av.x), ay = pk2(av.y, av.y);
            ull az = pk2(av.z, av.z), aw = pk2(av.w, av.w);
            acc2[r][0] = ff2(w0.x, ax, acc2[r][0]); acc2[r][1] = ff2(w0.y, ax, acc2[r][1]);
            acc2[r][0] = ff2(w1.x, ay, acc2[r][0]); acc2[r][1] = ff2(w1.y, ay, acc2[r][1]);
            acc2[r][0] = ff2(w2.x, az, acc2[r][0]); acc2[r][1] = ff2(w2.y, az, acc2[r][1]);
            acc2[r][0] = ff2(w3.x, aw, acc2[r][0]); acc2[r][1] = ff2(w3.y, aw, acc2[r][1]);
        }
    }
    #pragma unroll
    for (int r = 0; r < 4; r++) {
        float2 lo = up2(acc2[r][0]), hi = up2(acc2[r][1]);
        float4 o; o.x = lo.x; o.y = lo.y; o.z = hi.x; o.w = hi.y;
        *(float4*)&dst[(g0 + rg*4 + r)*64 + og*4] = o;
    }
}

// ---------------- merged tiled transpose ----------------
__global__ void k_transp(const float* __restrict__ src, float* __restrict__ dstM,
                         float* __restrict__ dstH) {
    __shared__ float t[32][33];
    int bx = blockIdx.x;
    const float* s; float* dst; int P;
    if (bx < 512) { s = src; dst = dstM; P = 16384; }
    else { s = src + HOFF*64; dst = dstH; P = 1024; bx -= 512; }
    int p0 = bx*32, c0 = blockIdx.y*32, b = blockIdx.z;
    int tx = threadIdx.x, ty = threadIdx.y;
    #pragma unroll
    for (int i = ty; i < 32; i += 8)
        t[i][tx] = s[((size_t)b*64 + c0 + i)*P + p0 + tx];
    __syncthreads();
    #pragma unroll
    for (int i = ty; i < 32; i += 8)
        dst[((size_t)b*P + p0 + i)*64 + c0 + tx] = t[tx][i];
}

// ---------------- fused MLP tail (f32x2) ----------------
#define TO_W3 33792
#define TO_H1 38016
#define TO_PR (38016 + 8448)
#define TO_PS 55424
#define TO_TOT 55616

__global__ void k_tail(const float* __restrict__ F1, const float* __restrict__ G1,
                       const float* __restrict__ Wr_g, const float* __restrict__ b2g,
                       const float* __restrict__ W2Tg, const float* __restrict__ W3g,
                       const float* __restrict__ b3g, float* __restrict__ outp) {
    extern __shared__ float sm[];
    float* sW2 = sm;
    float* sW3 = sm + TO_W3;
    float* h1T = sm + TO_H1;
    float* h2  = sm + TO_H1;
    float* prs = sm + TO_PR;
    int*   frowS = (int*)(sm + TO_PS);
    float* relYS = sm + TO_PS + 64;
    float* relXS = sm + TO_PS + 128;
    int tid = threadIdx.x;
    for (int i = tid; i < 32768; i += 256) { int k = i >> 7, j = i & 127; sW2[k*132 + j] = W2Tg[i]; }
    for (int i = tid; i < 4096;  i += 256) { int c = i >> 7, k = i & 127; sW3[c*132 + k] = W3g[i]; }
    float w0 = Wr_g[tid*2], w1 = Wr_g[tid*2 + 1];
    int jg = tid & 31, ig = tid >> 5;
    int j0 = jg*4, i0 = ig*8;
    float4 b2v = *(const float4*)(b2g + j0);
    float b3c = b3g[jg];
    __syncthreads();

    for (int pp = 0; pp < 4; pp++) {
        int pixA = blockIdx.x*64 + pp*16;
        if (tid < 64) {
            int pl = tid >> 2, s = tid & 3;
            int pix = pixA + pl;
            int yy = (pix >> 7) & 127, xx = pix & 127, bb = pix >> 14;
            float sy = (s & 2) ? 0.5f : -0.5f;
            float sx = (s & 1) ? 0.5f : -0.5f;
            int iyr = __float2int_rn((float)(2*yy+1)*0.125f - 0.5f + sy);
            int ixr = __float2int_rn((float)(2*xx+1)*0.125f - 0.5f + sx);
            if (iyr >= 0 && iyr < 32 && ixr >= 0 && ixr < 32) {
                frowS[tid] = bb*1024 + iyr*32 + ixr;
                relYS[tid] = (float)(2*yy+1)*0.25f - (float)(2*iyr+1);
                relXS[tid] = (float)(2*xx+1)*0.25f - (float)(2*ixr+1);
            } else {
                frowS[tid] = -1;
                relYS[tid] = (float)(2*yy+1)*0.25f - 32.f;
                relXS[tid] = (float)(2*xx+1)*0.25f - 32.f;
            }
        }
        __syncthreads();
        for (int pl = 0; pl < 16; pl++) {
            float g = G1[(size_t)(pixA + pl)*256 + tid];
            float4 vv;
            #pragma unroll
            for (int s = 0; s < 4; s++) {
                int inst = pl*4 + s;
                int fr = frowS[inst];
                float fv = (fr >= 0) ? F1[(size_t)fr*256 + tid] : 0.f;
                float v = g + fv + w0*relYS[inst] + w1*relXS[inst];
                (&vv.x)[s] = fmaxf(v, 0.f);
            }
            *(float4*)&h1T[tid*68 + pl*4] = vv;
        }
        __syncthreads();
        ull acc2[8][2];
        #pragma unroll
        for (int r = 0; r < 8; r++) { acc2[r][0] = pk2(b2v.x, b2v.y); acc2[r][1] = pk2(b2v.z, b2v.w); }
        #pragma unroll 2
        for (int k = 0; k < 256; k++) {
            ulonglong2 wu = *(const ulonglong2*)&sW2[k*132 + j0];
            float ha[8];
            *(float4*)&ha[0] = *(const float4*)&h1T[k*68 + i0];
            *(float4*)&ha[4] = *(const float4*)&h1T[k*68 + i0 + 4];
            #pragma unroll
            for (int r = 0; r < 8; r++) {
                ull au = pk2(ha[r], ha[r]);
                acc2[r][0] = ff2(wu.x, au, acc2[r][0]);
                acc2[r][1] = ff2(wu.y, au, acc2[r][1]);
            }
        }
        __syncthreads();
        #pragma unroll
        for (int r = 0; r < 8; r++) {
            float2 lo = up2(acc2[r][0]), hi = up2(acc2[r][1]);
            float4 hv;
            hv.x = fmaxf(lo.x, 0.f); hv.y = fmaxf(lo.y, 0.f);
            hv.z = fmaxf(hi.x, 0.f); hv.w = fmaxf(hi.y, 0.f);
            *(float4*)&h2[(i0 + r)*132 + j0] = hv;
        }
        __syncthreads();
        {
            ull a2[8];
            #pragma unroll
            for (int r = 0; r < 8; r++) a2[r] = pk2(b3c, 0.f);
            const float* wrow = &sW3[jg*132];
            #pragma unroll 2
            for (int k = 0; k < 128; k += 4) {
                ulonglong2 wu = *(const ulonglong2*)&wrow[k];
                #pragma unroll
                for (int r = 0; r < 8; r++) {
                    ulonglong2 hu = *(const ulonglong2*)&h2[(i0 + r)*132 + k];
                    a2[r] = ff2(wu.x, hu.x, a2[r]);
                    a2[r] = ff2(wu.y, hu.y, a2[r]);
                }
            }
            #pragma unroll
            for (int r = 0; r < 8; r++) {
                float2 p = up2(a2[r]);
                prs[(i0 + r)*36 + jg] = p.x + p.y;
            }
        }
        __syncthreads();
        for (int i = tid; i < 496; i += 256) {
            int pl = i / 31, c = i % 31;
            int base = pl*4;
            float l0 = prs[(base+0)*36 + 31];
            float l1 = prs[(base+1)*36 + 31];
            float l2 = prs[(base+2)*36 + 31];
            float l3 = prs[(base+3)*36 + 31];
            float m = fmaxf(fmaxf(l0, l1), fmaxf(l2, l3));
            float e0 = __expf(l0 - m), e1 = __expf(l1 - m);
            float e2 = __expf(l2 - m), e3 = __expf(l3 - m);
            float inv = 1.f / (e0 + e1 + e2 + e3);
            float v = (prs[(base+0)*36 + c]*e0 + prs[(base+1)*36 + c]*e1
                     + prs[(base+2)*36 + c]*e2 + prs[(base+3)*36 + c]*e3) * inv;
            int pix = pixA + pl;
            int bb = pix >> 14, yy = (pix >> 7) & 127, xx = pix & 127;
            outp[((size_t)bb*31 + c)*16384 + yy*128 + xx] = v;
        }
        __syncthreads();
    }
}

// ---------------- host ----------------
#define SMM_A ((64*256 + 32*64)*4)

extern "C" void kernel_launch(void* const* d_in, const int* in_sizes, int n_in,
                              void* d_out, int out_size) {
    const float* hsi  = (const float*)d_in[0];
    const float* msi  = (const float*)d_in[1];
    const float* ehw  = (const float*)d_in[2];
    const float* ehb  = (const float*)d_in[3];
    const float* emw  = (const float*)d_in[4];
    const float* emb  = (const float*)d_in[5];
    const float* Win  = (const float*)d_in[6];
    const float* convw= (const float*)d_in[7];
    const float* convb= (const float*)d_in[8];
    const float* Wxp  = (const float*)d_in[9];
    const float* Wdt  = (const float*)d_in[10];
    const float* bdt  = (const float*)d_in[11];
    const float* Alog = (const float*)d_in[12];
    const float* Dp   = (const float*)d_in[13];
    const float* Wout = (const float*)d_in[14];
    const float* W1   = (const float*)d_in[15];
    const float* b1   = (const float*)d_in[16];
    const float* W2   = (const float*)d_in[17];
    const float* b2   = (const float*)d_in[18];
    const float* W3   = (const float*)d_in[19];
    const float* b3   = (const float*)d_in[20];
    float* outp = (float*)d_out;

    float *tokA, *tokB, *xz, *u, *dt, *bc, *hend, *hinit, *sdt, *featT, *guideT, *F1, *G1;
    float *WinT, *WoutT, *W1fT, *W1gT, *Wr, *W2T, *WxpP, *WdtT, *cwT;
    cudaGetSymbolAddress((void**)&tokA, g_tokA);
    cudaGetSymbolAddress((void**)&tokB, g_tokB);
    cudaGetSymbolAddress((void**)&xz, g_xz);
    cudaGetSymbolAddress((void**)&u, g_u);
    cudaGetSymbolAddress((void**)&dt, g_dt);
    cudaGetSymbolAddress((void**)&bc, g_bc);
    cudaGetSymbolAddress((void**)&hend, g_hend);
    cudaGetSymbolAddress((void**)&hinit, g_hinit);
    cudaGetSymbolAddress((void**)&sdt, g_sdt);
    cudaGetSymbolAddress((void**)&featT, g_featT);
    cudaGetSymbolAddress((void**)&guideT, g_guideT);
    cudaGetSymbolAddress((void**)&F1, g_F1);
    cudaGetSymbolAddress((void**)&G1, g_G1);
    cudaGetSymbolAddress((void**)&WinT, g_WinT);
    cudaGetSymbolAddress((void**)&WoutT, g_WoutT);
    cudaGetSymbolAddress((void**)&W1fT, g_W1fT);
    cudaGetSymbolAddress((void**)&W1gT, g_W1gT);
    cudaGetSymbolAddress((void**)&Wr, g_Wr);
    cudaGetSymbolAddress((void**)&W2T, g_W2T);
    cudaGetSymbolAddress((void**)&WxpP, g_WxpP);
    cudaGetSymbolAddress((void**)&WdtT, g_WdtT);
    cudaGetSymbolAddress((void**)&cwT, g_cwT);

    cudaFuncSetAttribute(k_mmT<64,256,8>, cudaFuncAttributeMaxDynamicSharedMemorySize, SMM_A);
    cudaFuncSetAttribute(k_cps1, cudaFuncAttributeMaxDynamicSharedMemorySize, CP_TOT*4);
    cudaFuncSetAttribute(k_s2mm, cudaFuncAttributeMaxDynamicSharedMemorySize, S2_TOT*4);
    cudaFuncSetAttribute(k_tail, cudaFuncAttributeMaxDynamicSharedMemorySize, TO_TOT*4);

    k_prep<<<730, 256>>>(Win, Wout, W1, W2, Wxp, Wdt, convw,
                         WinT, WoutT, W1fT, W1gT, Wr, W2T, WxpP, WdtT, cwT);

    k_conv<<<17408, 256>>>(msi, hsi, emw, emb, ehw, ehb, tokA);

    const float* src = tokA;
    float* dst = tokB;
    int blks[2][2] = {{2, 0}, {3, 1}};
    for (int st = 0; st < 2; st++) {
        int bM = blks[st][0], bH = blks[st][1];
        k_mmT<64,256,8><<<2176, 256, SMM_A>>>(src, src + HOFF*64,
            WinT + bM*16384, WinT + bH*16384, nullptr, nullptr,
            xz, xz + (size_t)HOFF*256, 2048);
        k_cps1<<<1088, 256, CP_TOT*4>>>(xz, cwT, convb, WxpP, WdtT, bdt, Alog,
                                        u, dt, bc, hend, sdt, bM, bH);
        k_carry<<<16, 1024>>>(hend, sdt, Alog, hinit, bM, bH);
        k_s2mm<<<1088, 256, S2_TOT*4>>>(dt, u, bc, Alog, hinit, xz, Dp,
                                        WoutT, dst, bM, bH);
        const float* t2 = dst; dst = (float*)src; src = t2;
    }
    { dim3 g(544, 2, 4), blkd(32, 8); k_transp<<<g, blkd>>>(src, guideT, featT); }

    k_mmT<64,256,8><<<2176, 256, SMM_A>>>(guideT, featT, W1gT, W1fT, b1, nullptr, G1, F1, 2048);
    k_tail<<<1024, 256, TO_TOT*4>>>(F1, G1, Wr, b2, W2T, W3, b3, outp);
}

// round 12
// speedup vs baseline: 1.0354x; 1.0354x over previous
#include <cuda_runtime.h>
#include <cuda_bf16.h>
#include <math.h>

#define RTOT 69632
#define HOFF 65536
typedef unsigned long long ull;

__device__ __forceinline__ ull pk2(float a, float b) {
    ull r; asm("mov.b64 %0,{%1,%2};" : "=l"(r) : "f"(a), "f"(b)); return r;
}
__device__ __forceinline__ ull ff2(ull a, ull b, ull c) {
    ull d; asm("fma.rn.f32x2 %0,%1,%2,%3;" : "=l"(d) : "l"(a), "l"(b), "l"(c)); return d;
}
__device__ __forceinline__ float2 up2(ull v) {
    float2 f; asm("mov.b64 {%0,%1},%2;" : "=f"(f.x), "=f"(f.y) : "l"(v)); return f;
}

// ---------------- scratch ----------------
__device__ float g_tokA[RTOT*64];
__device__ float g_tokB[RTOT*64];
__device__ float g_xz  [RTOT*256];
__device__ float g_u   [RTOT*128];
__device__ float g_dt  [RTOT*128];
__device__ float g_bc  [RTOT*32];
__device__ float g_yz  [RTOT*128];
__device__ float g_hend [1088*2048];
__device__ float g_hinit[1088*2048];
__device__ float g_sdt  [1088*128];
__device__ float g_featT[4096*64];
__device__ float g_guideT[65536*64];
__device__ float g_F1[4096*256];
__device__ float g_G1[65536*256];
__device__ float g_WinT[4*16384];
__device__ float g_WoutT[4*8192];
__device__ float g_W1fT[16384];
__device__ float g_W1gT[16384];
__device__ float g_Wr[512];
__device__ float g_W2T[32768];
__device__ float g_WxpP[4*4752];
__device__ float g_WdtT[4*512];
__device__ float g_cwT[4*512];

// ---------------- one-shot weight prep ----------------
__global__ void k_prep(const float* __restrict__ Win, const float* __restrict__ Wout,
                       const float* __restrict__ W1, const float* __restrict__ W2,
                       const float* __restrict__ Wxp, const float* __restrict__ Wdt,
                       const float* __restrict__ convw,
                       float* WinT, float* WoutT, float* W1fT, float* W1gT, float* Wr,
                       float* W2T, float* WxpP, float* WdtT, float* cwT) {
    int i = blockIdx.x*256 + threadIdx.x;
    if (i < 65536) { int blk=i>>14, r=i&16383, k=r>>8, o=r&255; WinT[i]=Win[blk*16384+o*64+k]; return; }
    i -= 65536;
    if (i < 32768) { int blk=i>>13, r=i&8191, k=r>>6, o=r&63; WoutT[i]=Wout[blk*8192+o*128+k]; return; }
    i -= 32768;
    if (i < 16384) { int k=i>>8, o=i&255; W1fT[i]=W1[o*130+k]; return; }
    i -= 16384;
    if (i < 16384) { int k=i>>8, o=i&255; W1gT[i]=W1[o*130+64+k]; return; }
    i -= 16384;
    if (i < 512)   { Wr[i]=W1[(i>>1)*130+128+(i&1)]; return; }
    i -= 512;
    if (i < 32768) { int k=i>>7, j=i&127; W2T[i]=W2[j*256+k]; return; }
    i -= 32768;
    if (i < 18432) { int blk=i/4608, r=i%4608; WxpP[blk*4752 + (r>>7)*132 + (r&127)] = Wxp[i]; return; }
    i -= 18432;
    if (i < 2048)  { int blk=i>>9, rr=i&511, r=rr>>7, d=rr&127; WdtT[i]=Wdt[blk*512+d*4+r]; return; }
    i -= 2048;
    if (i < 2048)  { int blk=i>>9, rr=i&511, j=rr>>7, d=rr&127; cwT[i]=convw[blk*512+d*4+j]; return; }
}

// ---------------- merged encoder conv ----------------
__global__ void k_conv(const float* __restrict__ msi, const float* __restrict__ hsi,
                       const float* __restrict__ emw, const float* __restrict__ emb,
                       const float* __restrict__ ehw, const float* __restrict__ ehb,
                       float* __restrict__ outp) {
    if (blockIdx.x < 16384) {
        int idx = blockIdx.x*256 + threadIdx.x;
        int x = idx & 127, y = (idx >> 7) & 127, co = (idx >> 14) & 63, b = idx >> 20;
        float acc = emb[co];
        #pragma unroll
        for (int ci = 0; ci < 4; ci++)
            #pragma unroll
            for (int ky = 0; ky < 3; ky++) {
                int yy = y + ky - 1; if (yy < 0 || yy >= 128) continue;
                #pragma unroll
                for (int kx = 0; kx < 3; kx++) {
                    int xx = x + kx - 1; if (xx < 0 || xx >= 128) continue;
                    acc += emw[((co*4 + ci)*3 + ky)*3 + kx] * msi[((b*4 + ci)*128 + yy)*128 + xx];
                }
            }
        outp[idx] = fmaxf(acc, 0.f);
    } else {
        int idx = (blockIdx.x - 16384)*256 + threadIdx.x;
        int x = idx & 31, y = (idx >> 5) & 31, co = (idx >> 10) & 63, b = idx >> 16;
        float acc = ehb[co];
        for (int ci = 0; ci < 31; ci++)
            #pragma unroll
            for (int ky = 0; ky < 3; ky++) {
                int yy = y + ky - 1; if (yy < 0 || yy >= 32) continue;
                #pragma unroll
                for (int kx = 0; kx < 3; kx++) {
                    int xx = x + kx - 1; if (xx < 0 || xx >= 32) continue;
                    acc += ehw[((co*31 + ci)*3 + ky)*3 + kx] * hsi[((b*31 + ci)*32 + yy)*32 + xx];
                }
            }
        outp[HOFF*64 + idx] = fmaxf(acc, 0.f);
    }
}

// ---------------- merged matmul (f32x2) ----------------
template<int IN, int OUT, int RT>
__global__ void k_mmT(const float* __restrict__ Xm, const float* __restrict__ Xh,
                      const float* __restrict__ Wm, const float* __restrict__ Wh,
                      const float* __restrict__ bm, const float* __restrict__ bh,
                      float* __restrict__ Ym, float* __restrict__ Yh, int HB) {
    constexpr int nOG = OUT/4;
    constexpr int RB  = RT*(256/nOG);
    extern __shared__ float sm[];
    float* Ws = sm;
    float* Xs = sm + IN*OUT;
    int tid = threadIdx.x;
    const float *X, *WT, *bias; float* Y; size_t row0;
    if ((int)blockIdx.x < HB) { X=Xm; WT=Wm; bias=bm; Y=Ym; row0=(size_t)blockIdx.x*RB; }
    else { X=Xh; WT=Wh; bias=bh; Y=Yh; row0=(size_t)(blockIdx.x-HB)*RB; }
    for (int i = tid; i < OUT*IN/4; i += 256) ((float4*)Ws)[i] = ((const float4*)WT)[i];
    for (int i = tid; i < RB*IN/4; i += 256)
        ((float4*)Xs)[i] = ((const float4*)(X + row0*IN))[i];
    __syncthreads();
    int og = tid % nOG, rg = tid / nOG;
    float4 bv = bias ? *(const float4*)(bias + og*4) : make_float4(0.f,0.f,0.f,0.f);
    ull acc2[RT][2];
    #pragma unroll
    for (int r = 0; r < RT; r++) { acc2[r][0] = pk2(bv.x, bv.y); acc2[r][1] = pk2(bv.z, bv.w); }
    #pragma unroll 2
    for (int k = 0; k < IN; k += 4) {
        ulonglong2 w0 = *(const ulonglong2*)&Ws[(k+0)*OUT + og*4];
        ulonglong2 w1 = *(const ulonglong2*)&Ws[(k+1)*OUT + og*4];
        ulonglong2 w2 = *(const ulonglong2*)&Ws[(k+2)*OUT + og*4];
        ulonglong2 w3 = *(const ulonglong2*)&Ws[(k+3)*OUT + og*4];
        #pragma unroll
        for (int r = 0; r < RT; r++) {
            float4 av = *(const float4*)&Xs[(rg*RT + r)*IN + k];
            ull ax = pk2(av.x, av.x), ay = pk2(av.y, av.y);
            ull az = pk2(av.z, av.z), aw = pk2(av.w, av.w);
            acc2[r][0] = ff2(w0.x, ax, acc2[r][0]); acc2[r][1] = ff2(w0.y, ax, acc2[r][1]);
            acc2[r][0] = ff2(w1.x, ay, acc2[r][0]); acc2[r][1] = ff2(w1.y, ay, acc2[r][1]);
            acc2[r][0] = ff2(w2.x, az, acc2[r][0]); acc2[r][1] = ff2(w2.y, az, acc2[r][1]);
            acc2[r][0] = ff2(w3.x, aw, acc2[r][0]); acc2[r][1] = ff2(w3.y, aw, acc2[r][1]);
        }
    }
    #pragma unroll
    for (int r = 0; r < RT; r++) {
        float2 lo = up2(acc2[r][0]), hi = up2(acc2[r][1]);
        float4 o; o.x = lo.x; o.y = lo.y; o.z = hi.x; o.w = hi.y;
        *(float4*)&Y[(row0 + rg*RT + r)*OUT + og*4] = o;
    }
}

// ---------------- convproj (32 tok/block, o-major Wxp, conflict-free phase 2) ----------------
__global__ void k_convproj(const float* __restrict__ xz, const float* __restrict__ cwT,
        const float* __restrict__ convb, const float* __restrict__ WxpP,
        const float* __restrict__ WdtT, const float* __restrict__ bdt,
        float* __restrict__ u_out, float* __restrict__ dt_out, float* __restrict__ bc_out,
        int blkM, int blkH, int HB) {
    __shared__ float Wxps[4752], us[32*132], xds[32*40], Wdts[512], bdts[128], cws[512], cbs[128];
    int tid = threadIdx.x;
    int blk, g0, Lmask;
    if ((int)blockIdx.x < HB) { blk = blkM; g0 = blockIdx.x*32; Lmask = 16383; }
    else { blk = blkH; g0 = HOFF + (blockIdx.x - HB)*32; Lmask = 1023; }
    for (int i = tid; i < 4752; i += 256) Wxps[i] = WxpP[blk*4752 + i];
    for (int i = tid; i < 512; i += 256) { Wdts[i] = WdtT[blk*512 + i]; cws[i] = cwT[blk*512 + i]; }
    if (tid < 128) { bdts[tid] = bdt[blk*128 + tid]; cbs[tid] = convb[blk*128 + tid]; }
    __syncthreads();
    // phase 1: depthwise conv + silu (float4 over d)
    for (int i = tid; i < 1024; i += 256) {
        int tt = i >> 5, d4 = (i & 31)*4;
        int g = g0 + tt, t = g & Lmask;
        float4 acc = *(const float4*)&cbs[d4];
        #pragma unroll
        for (int j = 0; j < 4; j++) {
            if (t - 3 + j >= 0) {
                float4 xv = *(const float4*)&xz[(size_t)(g-3+j)*256 + d4];
                float4 wv = *(const float4*)&cws[j*128 + d4];
                acc.x += wv.x*xv.x; acc.y += wv.y*xv.y; acc.z += wv.z*xv.z; acc.w += wv.w*xv.w;
            }
        }
        float4 uu;
        uu.x = acc.x/(1.f+__expf(-acc.x)); uu.y = acc.y/(1.f+__expf(-acc.y));
        uu.z = acc.z/(1.f+__expf(-acc.z)); uu.w = acc.w/(1.f+__expf(-acc.w));
        *(float4*)&us[tt*132 + d4] = uu;
        *(float4*)&u_out[(size_t)g*128 + d4] = uu;
    }
    __syncthreads();
    // phase 2: xdbl = u @ Wxp^T; tt-fast lanes, broadcast weights, conflict-free us
    for (int i = tid; i < 576; i += 256) {
        int tt = i & 31, op = i >> 5;
        int o0 = op*2;
        const float* up  = &us[tt*132];
        const float* w0p = &Wxps[o0*132];
        const float* w1p = &Wxps[o0*132 + 132];
        float a0 = 0.f, a1 = 0.f;
        #pragma unroll 4
        for (int k = 0; k < 128; k += 4) {
            float4 uv = *(const float4*)&up[k];
            float4 w0 = *(const float4*)&w0p[k];
            float4 w1 = *(const float4*)&w1p[k];
            a0 += w0.x*uv.x + w0.y*uv.y + w0.z*uv.z + w0.w*uv.w;
            a1 += w1.x*uv.x + w1.y*uv.y + w1.z*uv.z + w1.w*uv.w;
        }
        xds[tt*40 + o0] = a0; xds[tt*40 + o0 + 1] = a1;
    }
    __syncthreads();
    // phase 3: bc out + dt
    for (int i = tid; i < 1024; i += 256) {
        int tt = i >> 5;
        bc_out[(size_t)(g0+tt)*32 + (i & 31)] = xds[tt*40 + (i & 31) + 4];
    }
    for (int i = tid; i < 1024; i += 256) {
        int tt = i >> 5, d4 = (i & 31)*4;
        float4 dtp = *(const float4*)&bdts[d4];
        #pragma unroll
        for (int r = 0; r < 4; r++) {
            float x = xds[tt*40 + r];
            float4 wv = *(const float4*)&Wdts[r*128 + d4];
            dtp.x += x*wv.x; dtp.y += x*wv.y; dtp.z += x*wv.z; dtp.w += x*wv.w;
        }
        float4 o;
        o.x = (dtp.x > 20.f) ? dtp.x : log1pf(__expf(dtp.x));
        o.y = (dtp.y > 20.f) ? dtp.y : log1pf(__expf(dtp.y));
        o.z = (dtp.z > 20.f) ? dtp.z : log1pf(__expf(dtp.z));
        o.w = (dtp.w > 20.f) ? dtp.w : log1pf(__expf(dtp.w));
        *(float4*)&dt_out[(size_t)(g0+tt)*128 + d4] = o;
    }
}

// ---------------- scan helpers ----------------
__device__ __forceinline__ bool load_A(const float* Alog, int d, float* An) {
    #pragma unroll
    for (int n = 0; n < 16; n++) An[n] = -__expf(Alog[d*16 + n]);
    bool geom = true;
    #pragma unroll
    for (int n = 1; n < 16; n++)
        if (fabsf(An[n] - (float)(n+1)*An[0]) > 1e-4f*(float)(n+1)) geom = false;
    return geom;
}

__global__ void k_scan1(const float* __restrict__ dt_a, const float* __restrict__ u_a,
                        const float* __restrict__ bc_a, const float* __restrict__ Alog,
                        float* __restrict__ hend, float* __restrict__ sdt_out,
                        int blkM, int blkH) {
    extern __shared__ float smS[];
    float* dtS = smS;
    float* uS  = smS + 64*128;
    float* bcS = smS + 64*256;
    int chunk = blockIdx.x;
    int d = threadIdx.x;
    const float* Al = Alog + ((chunk < 1024) ? blkM : blkH)*2048;
    size_t base = (size_t)chunk*64;
    const float4* dg = (const float4*)(dt_a + base*128);
    const float4* ug = (const float4*)(u_a + base*128);
    const float4* bg = (const float4*)(bc_a + base*32);
    for (int i = d; i < 64*32; i += 128) { ((float4*)dtS)[i] = dg[i]; ((float4*)uS)[i] = ug[i]; }
    for (int i = d; i < 64*8;  i += 128) ((float4*)bcS)[i] = bg[i];
    __syncthreads();
    float An[16];
    bool geom = load_A(Al, d, An);
    float h[16];
    #pragma unroll
    for (int n = 0; n < 16; n++) h[n] = 0.f;
    float s = 0.f;
    for (int tt = 0; tt < 64; tt++) {
        float dt = dtS[tt*128 + d];
        float du = dt * uS[tt*128 + d];
        s += dt;
        const float* Bv = &bcS[tt*32];
        if (geom) {
            float ep[16];
            ep[0] = __expf(dt * An[0]);
            #pragma unroll
            for (int n = 1; n < 16; n++) ep[n] = ep[(n-1)>>1]*ep[n>>1];
            #pragma unroll
            for (int n = 0; n < 16; n++) h[n] = ep[n]*h[n] + du*Bv[n];
        } else {
            #pragma unroll
            for (int n = 0; n < 16; n++) h[n] = __expf(dt*An[n])*h[n] + du*Bv[n];
        }
    }
    float* he = hend + ((size_t)chunk*128 + d)*16;
    #pragma unroll
    for (int n = 0; n < 16; n++) he[n] = h[n];
    sdt_out[chunk*128 + d] = s;
}

__global__ void k_carry(const float* __restrict__ hend, const float* __restrict__ sdt,
                        const float* __restrict__ Alog, float* __restrict__ hinit,
                        int blkM, int blkH) {
    int blk = blockIdx.x;
    int tid = threadIdx.x;
    int NC, chunk0, half; const float* Al;
    if (blk < 8) { NC = 256; chunk0 = (blk >> 1)*256; half = blk & 1; Al = Alog + blkM*2048; }
    else { int i = blk - 8; NC = 16; chunk0 = 1024 + (i >> 1)*16; half = i & 1; Al = Alog + blkH*2048; }
    int d = half*64 + (tid >> 4), n = tid & 15;
    float An = -__expf(Al[d*16 + n]);
    float h = 0.f;
    for (int c0 = 0; c0 < NC; c0 += 8) {
        float e8[8], v8[8];
        #pragma unroll
        for (int j = 0; j < 8; j++) {
            size_t off = (size_t)(chunk0 + c0 + j)*2048 + half*1024 + tid;
            v8[j] = hend[off];
            e8[j] = __expf(sdt[(chunk0 + c0 + j)*128 + d]*An);
        }
        #pragma unroll
        for (int j = 0; j < 8; j++) {
            size_t off = (size_t)(chunk0 + c0 + j)*2048 + half*1024 + tid;
            hinit[off] = h;
            h = e8[j]*h + v8[j];
        }
    }
}

__global__ void k_scan2(const float* __restrict__ dt_a, const float* __restrict__ u_a,
                        const float* __restrict__ bc_a, const float* __restrict__ Alog,
                        const float* __restrict__ hinit, const float* __restrict__ xz,
                        const float* __restrict__ Dp, float* __restrict__ yz,
                        int blkM, int blkH) {
    extern __shared__ float smS[];
    float* dtS = smS;
    float* uS  = smS + 64*128;
    float* bcS = smS + 64*256;
    int chunk = blockIdx.x;
    int d = threadIdx.x;
    int blk = (chunk < 1024) ? blkM : blkH;
    const float* Al = Alog + blk*2048;
    size_t base = (size_t)chunk*64;
    const float4* dg = (const float4*)(dt_a + base*128);
    const float4* ug = (const float4*)(u_a + base*128);
    const float4* bg = (const float4*)(bc_a + base*32);
    for (int i = d; i < 64*32; i += 128) { ((float4*)dtS)[i] = dg[i]; ((float4*)uS)[i] = ug[i]; }
    for (int i = d; i < 64*8;  i += 128) ((float4*)bcS)[i] = bg[i];
    __syncthreads();
    float An[16];
    bool geom = load_A(Al, d, An);
    float h[16];
    const float* hi = hinit + ((size_t)chunk*128 + d)*16;
    #pragma unroll
    for (int n = 0; n < 16; n++) h[n] = hi[n];
    float dcoef = Dp[blk*128 + d];
    for (int tt = 0; tt < 64; tt++) {
        size_t row = base + tt;
        float dt = dtS[tt*128 + d];
        float u  = uS[tt*128 + d];
        float du = dt * u;
        float y = 0.f;
        const float* Bv = &bcS[tt*32];
        if (geom) {
            float ep[16];
            ep[0] = __expf(dt * An[0]);
            #pragma unroll
            for (int n = 1; n < 16; n++) ep[n] = ep[(n-1)>>1]*ep[n>>1];
            #pragma unroll
            for (int n = 0; n < 16; n++) {
                h[n] = ep[n]*h[n] + du*Bv[n]; y += h[n]*Bv[16 + n];
            }
        } else {
            #pragma unroll
            for (int n = 0; n < 16; n++) {
                h[n] = __expf(dt*An[n])*h[n] + du*Bv[n]; y += h[n]*Bv[16 + n];
            }
        }
        float ys = y + u*dcoef;
        float z = xz[row*256 + 128 + d];
        float sz = z / (1.f + __expf(-z));
        yz[row*128 + d] = ys * sz;
    }
}

// ---------------- merged tiled transpose ----------------
__global__ void k_transp(const float* __restrict__ src, float* __restrict__ dstM,
                         float* __restrict__ dstH) {
    __shared__ float t[32][33];
    int bx = blockIdx.x;
    const float* s; float* dst; int P;
    if (bx < 512) { s = src; dst = dstM; P = 16384; }
    else { s = src + HOFF*64; dst = dstH; P = 1024; bx -= 512; }
    int p0 = bx*32, c0 = blockIdx.y*32, b = blockIdx.z;
    int tx = threadIdx.x, ty = threadIdx.y;
    #pragma unroll
    for (int i = ty; i < 32; i += 8)
        t[i][tx] = s[((size_t)b*64 + c0 + i)*P + p0 + tx];
    __syncthreads();
    #pragma unroll
    for (int i = ty; i < 32; i += 8)
        dst[((size_t)b*P + p0 + i)*64 + c0 + tx] = t[tx][i];
}

// ---------------- fused MLP tail (f32x2) ----------------
#define TO_W3 33792
#define TO_H1 38016
#define TO_PR (38016 + 8448)
#define TO_PS 55424
#define TO_TOT 55616

__global__ void k_tail(const float* __restrict__ F1, const float* __restrict__ G1,
                       const float* __restrict__ Wr_g, const float* __restrict__ b2g,
                       const float* __restrict__ W2Tg, const float* __restrict__ W3g,
                       const float* __restrict__ b3g, float* __restrict__ outp) {
    extern __shared__ float sm[];
    float* sW2 = sm;
    float* sW3 = sm + TO_W3;
    float* h1T = sm + TO_H1;
    float* h2  = sm + TO_H1;
    float* prs = sm + TO_PR;
    int*   frowS = (int*)(sm + TO_PS);
    float* relYS = sm + TO_PS + 64;
    float* relXS = sm + TO_PS + 128;
    int tid = threadIdx.x;
    for (int i = tid; i < 32768; i += 256) { int k = i >> 7, j = i & 127; sW2[k*132 + j] = W2Tg[i]; }
    for (int i = tid; i < 4096;  i += 256) { int c = i >> 7, k = i & 127; sW3[c*132 + k] = W3g[i]; }
    float w0 = Wr_g[tid*2], w1 = Wr_g[tid*2 + 1];
    int jg = tid & 31, ig = tid >> 5;
    int j0 = jg*4, i0 = ig*8;
    float4 b2v = *(const float4*)(b2g + j0);
    float b3c = b3g[jg];
    __syncthreads();

    for (int pp = 0; pp < 4; pp++) {
        int pixA = blockIdx.x*64 + pp*16;
        if (tid < 64) {
            int pl = tid >> 2, s = tid & 3;
            int pix = pixA + pl;
            int yy = (pix >> 7) & 127, xx = pix & 127, bb = pix >> 14;
            float sy = (s & 2) ? 0.5f : -0.5f;
            float sx = (s & 1) ? 0.5f : -0.5f;
            int iyr = __float2int_rn((float)(2*yy+1)*0.125f - 0.5f + sy);
            int ixr = __float2int_rn((float)(2*xx+1)*0.125f - 0.5f + sx);
            if (iyr >= 0 && iyr < 32 && ixr >= 0 && ixr < 32) {
                frowS[tid] = bb*1024 + iyr*32 + ixr;
                relYS[tid] = (float)(2*yy+1)*0.25f - (float)(2*iyr+1);
                relXS[tid] = (float)(2*xx+1)*0.25f - (float)(2*ixr+1);
            } else {
                frowS[tid] = -1;
                relYS[tid] = (float)(2*yy+1)*0.25f - 32.f;
                relXS[tid] = (float)(2*xx+1)*0.25f - 32.f;
            }
        }
        __syncthreads();
        for (int pl = 0; pl < 16; pl++) {
            float g = G1[(size_t)(pixA + pl)*256 + tid];
            float4 vv;
            #pragma unroll
            for (int s = 0; s < 4; s++) {
                int inst = pl*4 + s;
                int fr = frowS[inst];
                float fv = (fr >= 0) ? F1[(size_t)fr*256 + tid] : 0.f;
                float v = g + fv + w0*relYS[inst] + w1*relXS[inst];
                (&vv.x)[s] = fmaxf(v, 0.f);
            }
            *(float4*)&h1T[tid*68 + pl*4] = vv;
        }
        __syncthreads();
        ull acc2[8][2];
        #pragma unroll
        for (int r = 0; r < 8; r++) { acc2[r][0] = pk2(b2v.x, b2v.y); acc2[r][1] = pk2(b2v.z, b2v.w); }
        #pragma unroll 2
        for (int k = 0; k < 256; k++) {
            ulonglong2 wu = *(const ulonglong2*)&sW2[k*132 + j0];
            float ha[8];
            *(float4*)&ha[0] = *(const float4*)&h1T[k*68 + i0];
            *(float4*)&ha[4] = *(const float4*)&h1T[k*68 + i0 + 4];
            #pragma unroll
            for (int r = 0; r < 8; r++) {
                ull au = pk2(ha[r], ha[r]);
                acc2[r][0] = ff2(wu.x, au, acc2[r][0]);
                acc2[r][1] = ff2(wu.y, au, acc2[r][1]);
            }
        }
        __syncthreads();
        #pragma unroll
        for (int r = 0; r < 8; r++) {
            float2 lo = up2(acc2[r][0]), hi = up2(acc2[r][1]);
            float4 hv;
            hv.x = fmaxf(lo.x, 0.f); hv.y = fmaxf(lo.y, 0.f);
            hv.z = fmaxf(hi.x, 0.f); hv.w = fmaxf(hi.y, 0.f);
            *(float4*)&h2[(i0 + r)*132 + j0] = hv;
        }
        __syncthreads();
        {
            ull a2[8];
            #pragma unroll
            for (int r = 0; r < 8; r++) a2[r] = pk2(b3c, 0.f);
            const float* wrow = &sW3[jg*132];
            #pragma unroll 2
            for (int k = 0; k < 128; k += 4) {
                ulonglong2 wu = *(const ulonglong2*)&wrow[k];
                #pragma unroll
                for (int r = 0; r < 8; r++) {
                    ulonglong2 hu = *(const ulonglong2*)&h2[(i0 + r)*132 + k];
                    a2[r] = ff2(wu.x, hu.x, a2[r]);
                    a2[r] = ff2(wu.y, hu.y, a2[r]);
                }
            }
            #pragma unroll
            for (int r = 0; r < 8; r++) {
                float2 p = up2(a2[r]);
                prs[(i0 + r)*36 + jg] = p.x + p.y;
            }
        }
        __syncthreads();
        for (int i = tid; i < 496; i += 256) {
            int pl = i / 31, c = i % 31;
            int base = pl*4;
            float l0 = prs[(base+0)*36 + 31];
            float l1 = prs[(base+1)*36 + 31];
            float l2 = prs[(base+2)*36 + 31];
            float l3 = prs[(base+3)*36 + 31];
            float m = fmaxf(fmaxf(l0, l1), fmaxf(l2, l3));
            float e0 = __expf(l0 - m), e1 = __expf(l1 - m);
            float e2 = __expf(l2 - m), e3 = __expf(l3 - m);
            float inv = 1.f / (e0 + e1 + e2 + e3);
            float v = (prs[(base+0)*36 + c]*e0 + prs[(base+1)*36 + c]*e1
                     + prs[(base+2)*36 + c]*e2 + prs[(base+3)*36 + c]*e3) * inv;
            int pix = pixA + pl;
            int bb = pix >> 14, yy = (pix >> 7) & 127, xx = pix & 127;
            outp[((size_t)bb*31 + c)*16384 + yy*128 + xx] = v;
        }
        __syncthreads();
    }
}

// ---------------- host ----------------
#define SMM_A ((64*256 + 32*64)*4)
#define SMM_B ((128*64 + 128*128)*4)
#define SSC64 ((64*256 + 64*32)*4)

extern "C" void kernel_launch(void* const* d_in, const int* in_sizes, int n_in,
                              void* d_out, int out_size) {
    const float* hsi  = (const float*)d_in[0];
    const float* msi  = (const float*)d_in[1];
    const float* ehw  = (const float*)d_in[2];
    const float* ehb  = (const float*)d_in[3];
    const float* emw  = (const float*)d_in[4];
    const float* emb  = (const float*)d_in[5];
    const float* Win  = (const float*)d_in[6];
    const float* convw= (const float*)d_in[7];
    const float* convb= (const float*)d_in[8];
    const float* Wxp  = (const float*)d_in[9];
    const float* Wdt  = (const float*)d_in[10];
    const float* bdt  = (const float*)d_in[11];
    const float* Alog = (const float*)d_in[12];
    const float* Dp   = (const float*)d_in[13];
    const float* Wout = (const float*)d_in[14];
    const float* W1   = (const float*)d_in[15];
    const float* b1   = (const float*)d_in[16];
    const float* W2   = (const float*)d_in[17];
    const float* b2   = (const float*)d_in[18];
    const float* W3   = (const float*)d_in[19];
    const float* b3   = (const float*)d_in[20];
    float* outp = (float*)d_out;

    float *tokA, *tokB, *xz, *u, *dt, *bc, *yz, *hend, *hinit, *sdt, *featT, *guideT, *F1, *G1;
    float *WinT, *WoutT, *W1fT, *W1gT, *Wr, *W2T, *WxpP, *WdtT, *cwT;
    cudaGetSymbolAddress((void**)&tokA, g_tokA);
    cudaGetSymbolAddress((void**)&tokB, g_tokB);
    cudaGetSymbolAddress((void**)&xz, g_xz);
    cudaGetSymbolAddress((void**)&u, g_u);
    cudaGetSymbolAddress((void**)&dt, g_dt);
    cudaGetSymbolAddress((void**)&bc, g_bc);
    cudaGetSymbolAddress((void**)&yz, g_yz);
    cudaGetSymbolAddress((void**)&hend, g_hend);
    cudaGetSymbolAddress((void**)&hinit, g_hinit);
    cudaGetSymbolAddress((void**)&sdt, g_sdt);
    cudaGetSymbolAddress((void**)&featT, g_featT);
    cudaGetSymbolAddress((void**)&guideT, g_guideT);
    cudaGetSymbolAddress((void**)&F1, g_F1);
    cudaGetSymbolAddress((void**)&G1, g_G1);
    cudaGetSymbolAddress((void**)&WinT, g_WinT);
    cudaGetSymbolAddress((void**)&WoutT, g_WoutT);
    cudaGetSymbolAddress((void**)&W1fT, g_W1fT);
    cudaGetSymbolAddress((void**)&W1gT, g_W1gT);
    cudaGetSymbolAddress((void**)&Wr, g_Wr);
    cudaGetSymbolAddress((void**)&W2T, g_W2T);
    cudaGetSymbolAddress((void**)&WxpP, g_WxpP);
    cudaGetSymbolAddress((void**)&WdtT, g_WdtT);
    cudaGetSymbolAddress((void**)&cwT, g_cwT);

    cudaFuncSetAttribute(k_mmT<64,256,8>, cudaFuncAttributeMaxDynamicSharedMemorySize, SMM_A);
    cudaFuncSetAttribute(k_mmT<128,64,8>, cudaFuncAttributeMaxDynamicSharedMemorySize, SMM_B);
    cudaFuncSetAttribute(k_scan1, cudaFuncAttributeMaxDynamicSharedMemorySize, SSC64);
    cudaFuncSetAttribute(k_scan2, cudaFuncAttributeMaxDynamicSharedMemorySize, SSC64);
    cudaFuncSetAttribute(k_tail, cudaFuncAttributeMaxDynamicSharedMemorySize, TO_TOT*4);

    k_prep<<<730, 256>>>(Win, Wout, W1, W2, Wxp, Wdt, convw,
                         WinT, WoutT, W1fT, W1gT, Wr, W2T, WxpP, WdtT, cwT);

    k_conv<<<17408, 256>>>(msi, hsi, emw, emb, ehw, ehb, tokA);

    const float* src = tokA;
    float* dst = tokB;
    int blks[2][2] = {{2, 0}, {3, 1}};
    for (int st = 0; st < 2; st++) {
        int bM = blks[st][0], bH = blks[st][1];
        k_mmT<64,256,8><<<2176, 256, SMM_A>>>(src, src + HOFF*64,
            WinT + bM*16384, WinT + bH*16384, nullptr, nullptr,
            xz, xz + (size_t)HOFF*256, 2048);
        k_convproj<<<2176, 256>>>(xz, cwT, convb, WxpP, WdtT, bdt,
                                  u, dt, bc, bM, bH, 2048);
        k_scan1<<<1088, 128, SSC64>>>(dt, u, bc, Alog, hend, sdt, bM, bH);
        k_carry<<<16, 1024>>>(hend, sdt, Alog, hinit, bM, bH);
        k_scan2<<<1088, 128, SSC64>>>(dt, u, bc, Alog, hinit, xz, Dp, yz, bM, bH);
        k_mmT<128,64,8><<<544, 256, SMM_B>>>(yz, yz + (size_t)HOFF*128,
            WoutT + bM*8192, WoutT + bH*8192, nullptr, nullptr,
            dst, dst + HOFF*64, 512);
        const float* t2 = dst; dst = (float*)src; src = t2;
    }
    { dim3 g(544, 2, 4), blkd(32, 8); k_transp<<<g, blkd>>>(src, guideT, featT); }

    k_mmT<64,256,8><<<2176, 256, SMM_A>>>(guideT, featT, W1gT, W1fT, b1, nullptr, G1, F1, 2048);
    k_tail<<<1024, 256, TO_TOT*4>>>(F1, G1, Wr, b2, W2T, W3, b3, outp);
}

// round 15
// speedup vs baseline: 1.0814x; 1.0444x over previous
#include <cuda_runtime.h>
#include <cuda_bf16.h>
#include <math.h>

#define RTOT 69632
#define HOFF 65536
typedef unsigned long long ull;

__device__ __forceinline__ ull pk2(float a, float b) {
    ull r; asm("mov.b64 %0,{%1,%2};" : "=l"(r) : "f"(a), "f"(b)); return r;
}
__device__ __forceinline__ ull ff2(ull a, ull b, ull c) {
    ull d; asm("fma.rn.f32x2 %0,%1,%2,%3;" : "=l"(d) : "l"(a), "l"(b), "l"(c)); return d;
}
__device__ __forceinline__ float2 up2(ull v) {
    float2 f; asm("mov.b64 {%0,%1},%2;" : "=f"(f.x), "=f"(f.y) : "l"(v)); return f;
}

// ---------------- scratch ----------------
__device__ float g_tokA[RTOT*64];
__device__ float g_tokB[RTOT*64];
__device__ float g_xz  [RTOT*256];
__device__ float g_u   [RTOT*128];
__device__ float g_dt  [RTOT*128];
__device__ float g_bc  [RTOT*32];
__device__ float g_yz  [RTOT*128];
__device__ float g_hend [1088*2048];
__device__ float g_hinit[1088*2048];
__device__ float g_sdt  [1088*128];
__device__ float g_featT[4096*64];
__device__ float g_guideT[65536*64];
__device__ float g_F1[4096*256];
__device__ float g_G1[65536*256];
__device__ float g_WinT[4*16384];
__device__ float g_WoutT[4*8192];
__device__ float g_W1fT[16384];
__device__ float g_W1gT[16384];
__device__ float g_Wr[512];
__device__ float g_W2T[32768];
__device__ float g_WxpP[4*4752];
__device__ float g_WdtT[4*512];
__device__ float g_cwT[4*512];

// ---------------- one-shot weight prep ----------------
__global__ void k_prep(const float* __restrict__ Win, const float* __restrict__ Wout,
                       const float* __restrict__ W1, const float* __restrict__ W2,
                       const float* __restrict__ Wxp, const float* __restrict__ Wdt,
                       const float* __restrict__ convw,
                       float* WinT, float* WoutT, float* W1fT, float* W1gT, float* Wr,
                       float* W2T, float* WxpP, float* WdtT, float* cwT) {
    int i = blockIdx.x*256 + threadIdx.x;
    if (i < 65536) { int blk=i>>14, r=i&16383, k=r>>8, o=r&255; WinT[i]=Win[blk*16384+o*64+k]; return; }
    i -= 65536;
    if (i < 32768) { int blk=i>>13, r=i&8191, k=r>>6, o=r&63; WoutT[i]=Wout[blk*8192+o*128+k]; return; }
    i -= 32768;
    if (i < 16384) { int k=i>>8, o=i&255; W1fT[i]=W1[o*130+k]; return; }
    i -= 16384;
    if (i < 16384) { int k=i>>8, o=i&255; W1gT[i]=W1[o*130+64+k]; return; }
    i -= 16384;
    if (i < 512)   { Wr[i]=W1[(i>>1)*130+128+(i&1)]; return; }
    i -= 512;
    if (i < 32768) { int k=i>>7, j=i&127; W2T[i]=W2[j*256+k]; return; }
    i -= 32768;
    if (i < 18432) { int blk=i/4608, r=i%4608; WxpP[blk*4752 + (r>>7)*132 + (r&127)] = Wxp[i]; return; }
    i -= 18432;
    if (i < 2048)  { int blk=i>>9, rr=i&511, r=rr>>7, d=rr&127; WdtT[i]=Wdt[blk*512+d*4+r]; return; }
    i -= 2048;
    if (i < 2048)  { int blk=i>>9, rr=i&511, j=rr>>7, d=rr&127; cwT[i]=convw[blk*512+d*4+j]; return; }
}

// ---------------- merged encoder conv ----------------
__global__ void k_conv(const float* __restrict__ msi, const float* __restrict__ hsi,
                       const float* __restrict__ emw, const float* __restrict__ emb,
                       const float* __restrict__ ehw, const float* __restrict__ ehb,
                       float* __restrict__ outp) {
    if (blockIdx.x < 16384) {
        int idx = blockIdx.x*256 + threadIdx.x;
        int x = idx & 127, y = (idx >> 7) & 127, co = (idx >> 14) & 63, b = idx >> 20;
        float acc = emb[co];
        #pragma unroll
        for (int ci = 0; ci < 4; ci++)
            #pragma unroll
            for (int ky = 0; ky < 3; ky++) {
                int yy = y + ky - 1; if (yy < 0 || yy >= 128) continue;
                #pragma unroll
                for (int kx = 0; kx < 3; kx++) {
                    int xx = x + kx - 1; if (xx < 0 || xx >= 128) continue;
                    acc += emw[((co*4 + ci)*3 + ky)*3 + kx] * msi[((b*4 + ci)*128 + yy)*128 + xx];
                }
            }
        outp[idx] = fmaxf(acc, 0.f);
    } else {
        int idx = (blockIdx.x - 16384)*256 + threadIdx.x;
        int x = idx & 31, y = (idx >> 5) & 31, co = (idx >> 10) & 63, b = idx >> 16;
        float acc = ehb[co];
        for (int ci = 0; ci < 31; ci++)
            #pragma unroll
            for (int ky = 0; ky < 3; ky++) {
                int yy = y + ky - 1; if (yy < 0 || yy >= 32) continue;
                #pragma unroll
                for (int kx = 0; kx < 3; kx++) {
                    int xx = x + kx - 1; if (xx < 0 || xx >= 32) continue;
                    acc += ehw[((co*31 + ci)*3 + ky)*3 + kx] * hsi[((b*31 + ci)*32 + yy)*32 + xx];
                }
            }
        outp[HOFF*64 + idx] = fmaxf(acc, 0.f);
    }
}

// ---------------- merged matmul (f32x2) ----------------
template<int IN, int OUT, int RT>
__global__ void k_mmT(const float* __restrict__ Xm, const float* __restrict__ Xh,
                      const float* __restrict__ Wm, const float* __restrict__ Wh,
                      const float* __restrict__ bm, const float* __restrict__ bh,
                      float* __restrict__ Ym, float* __restrict__ Yh, int HB) {
    constexpr int nOG = OUT/4;
    constexpr int RB  = RT*(256/nOG);
    extern __shared__ float sm[];
    float* Ws = sm;
    float* Xs = sm + IN*OUT;
    int tid = threadIdx.x;
    const float *X, *WT, *bias; float* Y; size_t row0;
    if ((int)blockIdx.x < HB) { X=Xm; WT=Wm; bias=bm; Y=Ym; row0=(size_t)blockIdx.x*RB; }
    else { X=Xh; WT=Wh; bias=bh; Y=Yh; row0=(size_t)(blockIdx.x-HB)*RB; }
    for (int i = tid; i < OUT*IN/4; i += 256) ((float4*)Ws)[i] = ((const float4*)WT)[i];
    for (int i = tid; i < RB*IN/4; i += 256)
        ((float4*)Xs)[i] = ((const float4*)(X + row0*IN))[i];
    __syncthreads();
    int og = tid % nOG, rg = tid / nOG;
    float4 bv = bias ? *(const float4*)(bias + og*4) : make_float4(0.f,0.f,0.f,0.f);
    ull acc2[RT][2];
    #pragma unroll
    for (int r = 0; r < RT; r++) { acc2[r][0] = pk2(bv.x, bv.y); acc2[r][1] = pk2(bv.z, bv.w); }
    #pragma unroll 2
    for (int k = 0; k < IN; k += 4) {
        ulonglong2 w0 = *(const ulonglong2*)&Ws[(k+0)*OUT + og*4];
        ulonglong2 w1 = *(const ulonglong2*)&Ws[(k+1)*OUT + og*4];
        ulonglong2 w2 = *(const ulonglong2*)&Ws[(k+2)*OUT + og*4];
        ulonglong2 w3 = *(const ulonglong2*)&Ws[(k+3)*OUT + og*4];
        #pragma unroll
        for (int r = 0; r < RT; r++) {
            float4 av = *(const float4*)&Xs[(rg*RT + r)*IN + k];
            ull ax = pk2(av.x, av.x), ay = pk2(av.y, av.y);
            ull az = pk2(av.z, av.z), aw = pk2(av.w, av.w);
            acc2[r][0] = ff2(w0.x, ax, acc2[r][0]); acc2[r][1] = ff2(w0.y, ax, acc2[r][1]);
            acc2[r][0] = ff2(w1.x, ay, acc2[r][0]); acc2[r][1] = ff2(w1.y, ay, acc2[r][1]);
            acc2[r][0] = ff2(w2.x, az, acc2[r][0]); acc2[r][1] = ff2(w2.y, az, acc2[r][1]);
            acc2[r][0] = ff2(w3.x, aw, acc2[r][0]); acc2[r][1] = ff2(w3.y, aw, acc2[r][1]);
        }
    }
    #pragma unroll
    for (int r = 0; r < RT; r++) {
        float2 lo = up2(acc2[r][0]), hi = up2(acc2[r][1]);
        float4 o; o.x = lo.x; o.y = lo.y; o.z = hi.x; o.w = hi.y;
        *(float4*)&Y[(row0 + rg*RT + r)*OUT + og*4] = o;
    }
}

// ---------------- convproj ----------------
__global__ void k_convproj(const float* __restrict__ xz, const float* __restrict__ cwT,
        const float* __restrict__ convb, const float* __restrict__ WxpP,
        const float* __restrict__ WdtT, const float* __restrict__ bdt,
        float* __restrict__ u_out, float* __restrict__ dt_out, float* __restrict__ bc_out,
        int blkM, int blkH, int HB) {
    __shared__ float Wxps[4752], us[32*132], xds[32*40], Wdts[512], bdts[128], cws[512], cbs[128];
    int tid = threadIdx.x;
    int blk, g0, Lmask;
    if ((int)blockIdx.x < HB) { blk = blkM; g0 = blockIdx.x*32; Lmask = 16383; }
    else { blk = blkH; g0 = HOFF + (blockIdx.x - HB)*32; Lmask = 1023; }
    for (int i = tid; i < 4752; i += 256) Wxps[i] = WxpP[blk*4752 + i];
    for (int i = tid; i < 512; i += 256) { Wdts[i] = WdtT[blk*512 + i]; cws[i] = cwT[blk*512 + i]; }
    if (tid < 128) { bdts[tid] = bdt[blk*128 + tid]; cbs[tid] = convb[blk*128 + tid]; }
    __syncthreads();
    for (int i = tid; i < 1024; i += 256) {
        int tt = i >> 5, d4 = (i & 31)*4;
        int g = g0 + tt, t = g & Lmask;
        float4 acc = *(const float4*)&cbs[d4];
        #pragma unroll
        for (int j = 0; j < 4; j++) {
            if (t - 3 + j >= 0) {
                float4 xv = *(const float4*)&xz[(size_t)(g-3+j)*256 + d4];
                float4 wv = *(const float4*)&cws[j*128 + d4];
                acc.x += wv.x*xv.x; acc.y += wv.y*xv.y; acc.z += wv.z*xv.z; acc.w += wv.w*xv.w;
            }
        }
        float4 uu;
        uu.x = acc.x/(1.f+__expf(-acc.x)); uu.y = acc.y/(1.f+__expf(-acc.y));
        uu.z = acc.z/(1.f+__expf(-acc.z)); uu.w = acc.w/(1.f+__expf(-acc.w));
        *(float4*)&us[tt*132 + d4] = uu;
        *(float4*)&u_out[(size_t)g*128 + d4] = uu;
    }
    __syncthreads();
    for (int i = tid; i < 576; i += 256) {
        int tt = i & 31, op = i >> 5;
        int o0 = op*2;
        const float* up  = &us[tt*132];
        const float* w0p = &Wxps[o0*132];
        const float* w1p = &Wxps[o0*132 + 132];
        float a0 = 0.f, a1 = 0.f;
        #pragma unroll 4
        for (int k = 0; k < 128; k += 4) {
            float4 uv = *(const float4*)&up[k];
            float4 w0 = *(const float4*)&w0p[k];
            float4 w1 = *(const float4*)&w1p[k];
            a0 += w0.x*uv.x + w0.y*uv.y + w0.z*uv.z + w0.w*uv.w;
            a1 += w1.x*uv.x + w1.y*uv.y + w1.z*uv.z + w1.w*uv.w;
        }
        xds[tt*40 + o0] = a0; xds[tt*40 + o0 + 1] = a1;
    }
    __syncthreads();
    for (int i = tid; i < 1024; i += 256) {
        int tt = i >> 5;
        bc_out[(size_t)(g0+tt)*32 + (i & 31)] = xds[tt*40 + (i & 31) + 4];
    }
    for (int i = tid; i < 1024; i += 256) {
        int tt = i >> 5, d4 = (i & 31)*4;
        float4 dtp = *(const float4*)&bdts[d4];
        #pragma unroll
        for (int r = 0; r < 4; r++) {
            float x = xds[tt*40 + r];
            float4 wv = *(const float4*)&Wdts[r*128 + d4];
            dtp.x += x*wv.x; dtp.y += x*wv.y; dtp.z += x*wv.z; dtp.w += x*wv.w;
        }
        float4 o;
        o.x = (dtp.x > 20.f) ? dtp.x : log1pf(__expf(dtp.x));
        o.y = (dtp.y > 20.f) ? dtp.y : log1pf(__expf(dtp.y));
        o.z = (dtp.z > 20.f) ? dtp.z : log1pf(__expf(dtp.z));
        o.w = (dtp.w > 20.f) ? dtp.w : log1pf(__expf(dtp.w));
        *(float4*)&dt_out[(size_t)(g0+tt)*128 + d4] = o;
    }
}

// ---------------- scan ----------------
__device__ __forceinline__ bool load_A(const float* Alog, int d, float* An) {
    #pragma unroll
    for (int n = 0; n < 16; n++) An[n] = -__expf(Alog[d*16 + n]);
    bool geom = true;
    #pragma unroll
    for (int n = 1; n < 16; n++)
        if (fabsf(An[n] - (float)(n+1)*An[0]) > 1e-4f*(float)(n+1)) geom = false;
    return geom;
}

__global__ void k_scan1(const float* __restrict__ dt_a, const float* __restrict__ u_a,
                        const float* __restrict__ bc_a, const float* __restrict__ Alog,
                        float* __restrict__ hend, float* __restrict__ sdt_out,
                        int blkM, int blkH) {
    extern __shared__ float smS[];
    float* dtS = smS;
    float* uS  = smS + 64*128;
    float* bcS = smS + 64*256;
    int chunk = blockIdx.x;
    int d = threadIdx.x;
    const float* Al = Alog + ((chunk < 1024) ? blkM : blkH)*2048;
    size_t base = (size_t)chunk*64;
    const float4* dg = (const float4*)(dt_a + base*128);
    const float4* ug = (const float4*)(u_a + base*128);
    const float4* bg = (const float4*)(bc_a + base*32);
    for (int i = d; i < 64*32; i += 128) { ((float4*)dtS)[i] = dg[i]; ((float4*)uS)[i] = ug[i]; }
    for (int i = d; i < 64*8;  i += 128) ((float4*)bcS)[i] = bg[i];
    __syncthreads();
    float An[16];
    bool geom = load_A(Al, d, An);
    float h[16];
    #pragma unroll
    for (int n = 0; n < 16; n++) h[n] = 0.f;
    float s = 0.f;
    for (int tt = 0; tt < 64; tt++) {
        float dt = dtS[tt*128 + d];
        float du = dt * uS[tt*128 + d];
        s += dt;
        const float* Bv = &bcS[tt*32];
        if (geom) {
            float ep[16];
            ep[0] = __expf(dt * An[0]);
            #pragma unroll
            for (int n = 1; n < 16; n++) ep[n] = ep[(n-1)>>1]*ep[n>>1];
            #pragma unroll
            for (int n = 0; n < 16; n++) h[n] = ep[n]*h[n] + du*Bv[n];
        } else {
            #pragma unroll
            for (int n = 0; n < 16; n++) h[n] = __expf(dt*An[n])*h[n] + du*Bv[n];
        }
    }
    float* he = hend + ((size_t)chunk*128 + d)*16;
    #pragma unroll
    for (int n = 0; n < 16; n++) he[n] = h[n];
    sdt_out[chunk*128 + d] = s;
}

__global__ void k_carry(const float* __restrict__ hend, const float* __restrict__ sdt,
                        const float* __restrict__ Alog, float* __restrict__ hinit,
                        int blkM, int blkH) {
    int blk = blockIdx.x;
    int tid = threadIdx.x;
    int NC, chunk0, half; const float* Al;
    if (blk < 8) { NC = 256; chunk0 = (blk >> 1)*256; half = blk & 1; Al = Alog + blkM*2048; }
    else { int i = blk - 8; NC = 16; chunk0 = 1024 + (i >> 1)*16; half = i & 1; Al = Alog + blkH*2048; }
    int d = half*64 + (tid >> 4), n = tid & 15;
    float An = -__expf(Al[d*16 + n]);
    float h = 0.f;
    for (int c0 = 0; c0 < NC; c0 += 8) {
        float e8[8], v8[8];
        #pragma unroll
        for (int j = 0; j < 8; j++) {
            size_t off = (size_t)(chunk0 + c0 + j)*2048 + half*1024 + tid;
            v8[j] = hend[off];
            e8[j] = __expf(sdt[(chunk0 + c0 + j)*128 + d]*An);
        }
        #pragma unroll
        for (int j = 0; j < 8; j++) {
            size_t off = (size_t)(chunk0 + c0 + j)*2048 + half*1024 + tid;
            hinit[off] = h;
            h = e8[j]*h + v8[j];
        }
    }
}

__global__ void k_scan2(const float* __restrict__ dt_a, const float* __restrict__ u_a,
                        const float* __restrict__ bc_a, const float* __restrict__ Alog,
                        const float* __restrict__ hinit, const float* __restrict__ xz,
                        const float* __restrict__ Dp, float* __restrict__ yz,
                        int blkM, int blkH) {
    extern __shared__ float smS[];
    float* dtS = smS;
    float* uS  = smS + 64*128;
    float* bcS = smS + 64*256;
    int chunk = blockIdx.x;
    int d = threadIdx.x;
    int blk = (chunk < 1024) ? blkM : blkH;
    const float* Al = Alog + blk*2048;
    size_t base = (size_t)chunk*64;
    const float4* dg = (const float4*)(dt_a + base*128);
    const float4* ug = (const float4*)(u_a + base*128);
    const float4* bg = (const float4*)(bc_a + base*32);
    for (int i = d; i < 64*32; i += 128) { ((float4*)dtS)[i] = dg[i]; ((float4*)uS)[i] = ug[i]; }
    for (int i = d; i < 64*8;  i += 128) ((float4*)bcS)[i] = bg[i];
    __syncthreads();
    float An[16];
    bool geom = load_A(Al, d, An);
    float h[16];
    const float* hi = hinit + ((size_t)chunk*128 + d)*16;
    #pragma unroll
    for (int n = 0; n < 16; n++) h[n] = hi[n];
    float dcoef = Dp[blk*128 + d];
    for (int tt = 0; tt < 64; tt++) {
        size_t row = base + tt;
        float dt = dtS[tt*128 + d];
        float u  = uS[tt*128 + d];
        float du = dt * u;
        float y = 0.f;
        const float* Bv = &bcS[tt*32];
        if (geom) {
            float ep[16];
            ep[0] = __expf(dt * An[0]);
            #pragma unroll
            for (int n = 1; n < 16; n++) ep[n] = ep[(n-1)>>1]*ep[n>>1];
            #pragma unroll
            for (int n = 0; n < 16; n++) {
                h[n] = ep[n]*h[n] + du*Bv[n]; y += h[n]*Bv[16 + n];
            }
        } else {
            #pragma unroll
            for (int n = 0; n < 16; n++) {
                h[n] = __expf(dt*An[n])*h[n] + du*Bv[n]; y += h[n]*Bv[16 + n];
            }
        }
        float ys = y + u*dcoef;
        float z = xz[row*256 + 128 + d];
        float sz = z / (1.f + __expf(-z));
        yz[row*128 + d] = ys * sz;
    }
}

// ---------------- merged tiled transpose ----------------
__global__ void k_transp(const float* __restrict__ src, float* __restrict__ dstM,
                         float* __restrict__ dstH) {
    __shared__ float t[32][33];
    int bx = blockIdx.x;
    const float* s; float* dst; int P;
    if (bx < 512) { s = src; dst = dstM; P = 16384; }
    else { s = src + HOFF*64; dst = dstH; P = 1024; bx -= 512; }
    int p0 = bx*32, c0 = blockIdx.y*32, b = blockIdx.z;
    int tx = threadIdx.x, ty = threadIdx.y;
    #pragma unroll
    for (int i = ty; i < 32; i += 8)
        t[i][tx] = s[((size_t)b*64 + c0 + i)*P + p0 + tx];
    __syncthreads();
    #pragma unroll
    for (int i = ty; i < 32; i += 8)
        dst[((size_t)b*P + p0 + i)*64 + c0 + tx] = t[tx][i];
}

// ---------------- fused MLP tail (f32x2, weights streamed from L2) ----------------
// smem floats: h1T [k*68+inst] 17408 (h2 [inst*132+j] and prs [inst*36+c] alias inside)
//              ps 17408..17600
#define TP_PS 17408
#define TP_TOT 17600

__global__ void k_tail(const float* __restrict__ F1, const float* __restrict__ G1,
                       const float* __restrict__ Wr_g, const float* __restrict__ b2g,
                       const float* __restrict__ W2Tg, const float* __restrict__ W3g,
                       const float* __restrict__ b3g, float* __restrict__ outp) {
    extern __shared__ float sm[];
    float* h1T = sm;
    float* h2  = sm;
    float* prs = sm + 8448;
    int*   frowS = (int*)(sm + TP_PS);
    float* relYS = sm + TP_PS + 64;
    float* relXS = sm + TP_PS + 128;
    int tid = threadIdx.x;
    float w0 = Wr_g[tid*2], w1 = Wr_g[tid*2 + 1];
    int jg = tid & 31, ig = tid >> 5;
    int j0 = jg*4, i0 = ig*8;
    float4 b2v = *(const float4*)(b2g + j0);
    float b3c = b3g[jg];

    for (int pp = 0; pp < 4; pp++) {
        int pixA = blockIdx.x*64 + pp*16;
        if (tid < 64) {
            int pl = tid >> 2, s = tid & 3;
            int pix = pixA + pl;
            int yy = (pix >> 7) & 127, xx = pix & 127, bb = pix >> 14;
            float sy = (s & 2) ? 0.5f : -0.5f;
            float sx = (s & 1) ? 0.5f : -0.5f;
            int iyr = __float2int_rn((float)(2*yy+1)*0.125f - 0.5f + sy);
            int ixr = __float2int_rn((float)(2*xx+1)*0.125f - 0.5f + sx);
            if (iyr >= 0 && iyr < 32 && ixr >= 0 && ixr < 32) {
                frowS[tid] = bb*1024 + iyr*32 + ixr;
                relYS[tid] = (float)(2*yy+1)*0.25f - (float)(2*iyr+1);
                relXS[tid] = (float)(2*xx+1)*0.25f - (float)(2*ixr+1);
            } else {
                frowS[tid] = -1;
                relYS[tid] = (float)(2*yy+1)*0.25f - 32.f;
                relXS[tid] = (float)(2*xx+1)*0.25f - 32.f;
            }
        }
        __syncthreads();
        // layer 1: thread = output o; h1T[o][inst], float4 over 4 shifts
        for (int pl = 0; pl < 16; pl++) {
            float g = G1[(size_t)(pixA + pl)*256 + tid];
            float4 vv;
            #pragma unroll
            for (int s = 0; s < 4; s++) {
                int inst = pl*4 + s;
                int fr = frowS[inst];
                float fv = (fr >= 0) ? F1[(size_t)fr*256 + tid] : 0.f;
                float v = g + fv + w0*relYS[inst] + w1*relXS[inst];
                (&vv.x)[s] = fmaxf(v, 0.f);
            }
            *(float4*)&h1T[tid*68 + pl*4] = vv;
        }
        __syncthreads();
        // layer 2: weights streamed from L2 (W2T k-major, row stride 128)
        ull acc2[8][2];
        #pragma unroll
        for (int r = 0; r < 8; r++) { acc2[r][0] = pk2(b2v.x, b2v.y); acc2[r][1] = pk2(b2v.z, b2v.w); }
        #pragma unroll 4
        for (int k = 0; k < 256; k++) {
            ulonglong2 wu = *(const ulonglong2*)&W2Tg[k*128 + j0];
            float ha[8];
            *(float4*)&ha[0] = *(const float4*)&h1T[k*68 + i0];
            *(float4*)&ha[4] = *(const float4*)&h1T[k*68 + i0 + 4];
            #pragma unroll
            for (int r = 0; r < 8; r++) {
                ull au = pk2(ha[r], ha[r]);
                acc2[r][0] = ff2(wu.x, au, acc2[r][0]);
                acc2[r][1] = ff2(wu.y, au, acc2[r][1]);
            }
        }
        __syncthreads();   // h1T reads done before h2 (aliased) writes
        #pragma unroll
        for (int r = 0; r < 8; r++) {
            float2 lo = up2(acc2[r][0]), hi = up2(acc2[r][1]);
            float4 hv;
            hv.x = fmaxf(lo.x, 0.f); hv.y = fmaxf(lo.y, 0.f);
            hv.z = fmaxf(hi.x, 0.f); hv.w = fmaxf(hi.y, 0.f);
            *(float4*)&h2[(i0 + r)*132 + j0] = hv;
        }
        __syncthreads();
        // layer 3: W3 native row-major [c][k] is k-contiguous — stream from L2
        {
            ull a2[8];
            #pragma unroll
            for (int r = 0; r < 8; r++) a2[r] = pk2(b3c, 0.f);
            const float* wrow = W3g + jg*128;
            #pragma unroll 4
            for (int k = 0; k < 128; k += 4) {
                ulonglong2 wu = *(const ulonglong2*)&wrow[k];
                #pragma unroll
                for (int r = 0; r < 8; r++) {
                    ulonglong2 hu = *(const ulonglong2*)&h2[(i0 + r)*132 + k];
                    a2[r] = ff2(wu.x, hu.x, a2[r]);
                    a2[r] = ff2(wu.y, hu.y, a2[r]);
                }
            }
            #pragma unroll
            for (int r = 0; r < 8; r++) {
                float2 p = up2(a2[r]);
                prs[(i0 + r)*36 + jg] = p.x + p.y;
            }
        }
        __syncthreads();
        // softmax over 4 shifts + combine
        for (int i = tid; i < 496; i += 256) {
            int pl = i / 31, c = i % 31;
            int base = pl*4;
            float l0 = prs[(base+0)*36 + 31];
            float l1 = prs[(base+1)*36 + 31];
            float l2 = prs[(base+2)*36 + 31];
            float l3 = prs[(base+3)*36 + 31];
            float m = fmaxf(fmaxf(l0, l1), fmaxf(l2, l3));
            float e0 = __expf(l0 - m), e1 = __expf(l1 - m);
            float e2 = __expf(l2 - m), e3 = __expf(l3 - m);
            float inv = 1.f / (e0 + e1 + e2 + e3);
            float v = (prs[(base+0)*36 + c]*e0 + prs[(base+1)*36 + c]*e1
                     + prs[(base+2)*36 + c]*e2 + prs[(base+3)*36 + c]*e3) * inv;
            int pix = pixA + pl;
            int bb = pix >> 14, yy = (pix >> 7) & 127, xx = pix & 127;
            outp[((size_t)bb*31 + c)*16384 + yy*128 + xx] = v;
        }
        __syncthreads();
    }
}

// ---------------- host ----------------
#define SMM_A ((64*256 + 32*64)*4)
#define SMM_B ((128*64 + 128*128)*4)
#define SSC64 ((64*256 + 64*32)*4)

extern "C" void kernel_launch(void* const* d_in, const int* in_sizes, int n_in,
                              void* d_out, int out_size) {
    const float* hsi  = (const float*)d_in[0];
    const float* msi  = (const float*)d_in[1];
    const float* ehw  = (const float*)d_in[2];
    const float* ehb  = (const float*)d_in[3];
    const float* emw  = (const float*)d_in[4];
    const float* emb  = (const float*)d_in[5];
    const float* Win  = (const float*)d_in[6];
    const float* convw= (const float*)d_in[7];
    const float* convb= (const float*)d_in[8];
    const float* Wxp  = (const float*)d_in[9];
    const float* Wdt  = (const float*)d_in[10];
    const float* bdt  = (const float*)d_in[11];
    const float* Alog = (const float*)d_in[12];
    const float* Dp   = (const float*)d_in[13];
    const float* Wout = (const float*)d_in[14];
    const float* W1   = (const float*)d_in[15];
    const float* b1   = (const float*)d_in[16];
    const float* W2   = (const float*)d_in[17];
    const float* b2   = (const float*)d_in[18];
    const float* W3   = (const float*)d_in[19];
    const float* b3   = (const float*)d_in[20];
    float* outp = (float*)d_out;

    float *tokA, *tokB, *xz, *u, *dt, *bc, *yz, *hend, *hinit, *sdt, *featT, *guideT, *F1, *G1;
    float *WinT, *WoutT, *W1fT, *W1gT, *Wr, *W2T, *WxpP, *WdtT, *cwT;
    cudaGetSymbolAddress((void**)&tokA, g_tokA);
    cudaGetSymbolAddress((void**)&tokB, g_tokB);
    cudaGetSymbolAddress((void**)&xz, g_xz);
    cudaGetSymbolAddress((void**)&u, g_u);
    cudaGetSymbolAddress((void**)&dt, g_dt);
    cudaGetSymbolAddress((void**)&bc, g_bc);
    cudaGetSymbolAddress((void**)&yz, g_yz);
    cudaGetSymbolAddress((void**)&hend, g_hend);
    cudaGetSymbolAddress((void**)&hinit, g_hinit);
    cudaGetSymbolAddress((void**)&sdt, g_sdt);
    cudaGetSymbolAddress((void**)&featT, g_featT);
    cudaGetSymbolAddress((void**)&guideT, g_guideT);
    cudaGetSymbolAddress((void**)&F1, g_F1);
    cudaGetSymbolAddress((void**)&G1, g_G1);
    cudaGetSymbolAddress((void**)&WinT, g_WinT);
    cudaGetSymbolAddress((void**)&WoutT, g_WoutT);
    cudaGetSymbolAddress((void**)&W1fT, g_W1fT);
    cudaGetSymbolAddress((void**)&W1gT, g_W1gT);
    cudaGetSymbolAddress((void**)&Wr, g_Wr);
    cudaGetSymbolAddress((void**)&W2T, g_W2T);
    cudaGetSymbolAddress((void**)&WxpP, g_WxpP);
    cudaGetSymbolAddress((void**)&WdtT, g_WdtT);
    cudaGetSymbolAddress((void**)&cwT, g_cwT);

    cudaFuncSetAttribute(k_mmT<64,256,8>, cudaFuncAttributeMaxDynamicSharedMemorySize, SMM_A);
    cudaFuncSetAttribute(k_mmT<128,64,8>, cudaFuncAttributeMaxDynamicSharedMemorySize, SMM_B);
    cudaFuncSetAttribute(k_scan1, cudaFuncAttributeMaxDynamicSharedMemorySize, SSC64);
    cudaFuncSetAttribute(k_scan2, cudaFuncAttributeMaxDynamicSharedMemorySize, SSC64);
    cudaFuncSetAttribute(k_tail, cudaFuncAttributeMaxDynamicSharedMemorySize, TP_TOT*4);

    k_prep<<<730, 256>>>(Win, Wout, W1, W2, Wxp, Wdt, convw,
                         WinT, WoutT, W1fT, W1gT, Wr, W2T, WxpP, WdtT, cwT);

    k_conv<<<17408, 256>>>(msi, hsi, emw, emb, ehw, ehb, tokA);

    const float* src = tokA;
    float* dst = tokB;
    int blks[2][2] = {{2, 0}, {3, 1}};
    for (int st = 0; st < 2; st++) {
        int bM = blks[st][0], bH = blks[st][1];
        k_mmT<64,256,8><<<2176, 256, SMM_A>>>(src, src + HOFF*64,
            WinT + bM*16384, WinT + bH*16384, nullptr, nullptr,
            xz, xz + (size_t)HOFF*256, 2048);
        k_convproj<<<2176, 256>>>(xz, cwT, convb, WxpP, WdtT, bdt,
                                  u, dt, bc, bM, bH, 2048);
        k_scan1<<<1088, 128, SSC64>>>(dt, u, bc, Alog, hend, sdt, bM, bH);
        k_carry<<<16, 1024>>>(hend, sdt, Alog, hinit, bM, bH);
        k_scan2<<<1088, 128, SSC64>>>(dt, u, bc, Alog, hinit, xz, Dp, yz, bM, bH);
        k_mmT<128,64,8><<<544, 256, SMM_B>>>(yz, yz + (size_t)HOFF*128,
            WoutT + bM*8192, WoutT + bH*8192, nullptr, nullptr,
            dst, dst + HOFF*64, 512);
        const float* t2 = dst; dst = (float*)src; src = t2;
    }
    { dim3 g(544, 2, 4), blkd(32, 8); k_transp<<<g, blkd>>>(src, guideT, featT); }

    k_mmT<64,256,8><<<2176, 256, SMM_A>>>(guideT, featT, W1gT, W1fT, b1, nullptr, G1, F1, 2048);
    k_tail<<<1024, 256, TP_TOT*4>>>(F1, G1, Wr, b2, W2T, W3, b3, outp);
}

// round 16
// speedup vs baseline: 1.1008x; 1.0179x over previous
#include <cuda_runtime.h>
#include <cuda_bf16.h>
#include <math.h>

#define RTOT 69632
#define HOFF 65536
typedef unsigned long long ull;

__device__ __forceinline__ ull pk2(float a, float b) {
    ull r; asm("mov.b64 %0,{%1,%2};" : "=l"(r) : "f"(a), "f"(b)); return r;
}
__device__ __forceinline__ ull ff2(ull a, ull b, ull c) {
    ull d; asm("fma.rn.f32x2 %0,%1,%2,%3;" : "=l"(d) : "l"(a), "l"(b), "l"(c)); return d;
}
__device__ __forceinline__ float2 up2(ull v) {
    float2 f; asm("mov.b64 {%0,%1},%2;" : "=f"(f.x), "=f"(f.y) : "l"(v)); return f;
}
__device__ __forceinline__ float fsilu(float x) {
    return x * __fdividef(1.f, 1.f + __expf(-x));
}
__device__ __forceinline__ float fsoftplus(float x) {
    return (x > 20.f) ? x : __logf(1.f + __expf(x));
}

// ---------------- scratch ----------------
__device__ float g_tokA[RTOT*64];
__device__ float g_tokB[RTOT*64];
__device__ float g_xz  [RTOT*256];
__device__ float g_u   [RTOT*128];
__device__ float g_dt  [RTOT*128];
__device__ float g_bc  [RTOT*32];
__device__ float g_yz  [RTOT*128];
__device__ float g_hend [1088*2048];
__device__ float g_hinit[1088*2048];
__device__ float g_sdt  [1088*128];
__device__ float g_featT[4096*64];
__device__ float g_guideT[65536*64];
__device__ float g_F1[4096*256];
__device__ float g_G1[65536*256];
__device__ float g_WinT[4*16384];
__device__ float g_WoutT[4*8192];
__device__ float g_W1fT[16384];
__device__ float g_W1gT[16384];
__device__ float g_Wr[512];
__device__ float g_W2T[32768];
__device__ float g_WxpP[4*4752];
__device__ float g_WdtT[4*512];
__device__ float g_cwT[4*512];

// ---------------- one-shot weight prep ----------------
__global__ void k_prep(const float* __restrict__ Win, const float* __restrict__ Wout,
                       const float* __restrict__ W1, const float* __restrict__ W2,
                       const float* __restrict__ Wxp, const float* __restrict__ Wdt,
                       const float* __restrict__ convw,
                       float* WinT, float* WoutT, float* W1fT, float* W1gT, float* Wr,
                       float* W2T, float* WxpP, float* WdtT, float* cwT) {
    int i = blockIdx.x*256 + threadIdx.x;
    if (i < 65536) { int blk=i>>14, r=i&16383, k=r>>8, o=r&255; WinT[i]=Win[blk*16384+o*64+k]; return; }
    i -= 65536;
    if (i < 32768) { int blk=i>>13, r=i&8191, k=r>>6, o=r&63; WoutT[i]=Wout[blk*8192+o*128+k]; return; }
    i -= 32768;
    if (i < 16384) { int k=i>>8, o=i&255; W1fT[i]=W1[o*130+k]; return; }
    i -= 16384;
    if (i < 16384) { int k=i>>8, o=i&255; W1gT[i]=W1[o*130+64+k]; return; }
    i -= 16384;
    if (i < 512)   { Wr[i]=W1[(i>>1)*130+128+(i&1)]; return; }
    i -= 512;
    if (i < 32768) { int k=i>>7, j=i&127; W2T[i]=W2[j*256+k]; return; }
    i -= 32768;
    if (i < 18432) { int blk=i/4608, r=i%4608; WxpP[blk*4752 + (r>>7)*132 + (r&127)] = Wxp[i]; return; }
    i -= 18432;
    if (i < 2048)  { int blk=i>>9, rr=i&511, r=rr>>7, d=rr&127; WdtT[i]=Wdt[blk*512+d*4+r]; return; }
    i -= 2048;
    if (i < 2048)  { int blk=i>>9, rr=i&511, j=rr>>7, d=rr&127; cwT[i]=convw[blk*512+d*4+j]; return; }
}

// ---------------- merged encoder conv ----------------
__global__ void k_conv(const float* __restrict__ msi, const float* __restrict__ hsi,
                       const float* __restrict__ emw, const float* __restrict__ emb,
                       const float* __restrict__ ehw, const float* __restrict__ ehb,
                       float* __restrict__ outp) {
    if (blockIdx.x < 16384) {
        int idx = blockIdx.x*256 + threadIdx.x;
        int x = idx & 127, y = (idx >> 7) & 127, co = (idx >> 14) & 63, b = idx >> 20;
        float acc = emb[co];
        #pragma unroll
        for (int ci = 0; ci < 4; ci++)
            #pragma unroll
            for (int ky = 0; ky < 3; ky++) {
                int yy = y + ky - 1; if (yy < 0 || yy >= 128) continue;
                #pragma unroll
                for (int kx = 0; kx < 3; kx++) {
                    int xx = x + kx - 1; if (xx < 0 || xx >= 128) continue;
                    acc += emw[((co*4 + ci)*3 + ky)*3 + kx] * msi[((b*4 + ci)*128 + yy)*128 + xx];
                }
            }
        outp[idx] = fmaxf(acc, 0.f);
    } else {
        int idx = (blockIdx.x - 16384)*256 + threadIdx.x;
        int x = idx & 31, y = (idx >> 5) & 31, co = (idx >> 10) & 63, b = idx >> 16;
        float acc = ehb[co];
        for (int ci = 0; ci < 31; ci++)
            #pragma unroll
            for (int ky = 0; ky < 3; ky++) {
                int yy = y + ky - 1; if (yy < 0 || yy >= 32) continue;
                #pragma unroll
                for (int kx = 0; kx < 3; kx++) {
                    int xx = x + kx - 1; if (xx < 0 || xx >= 32) continue;
                    acc += ehw[((co*31 + ci)*3 + ky)*3 + kx] * hsi[((b*31 + ci)*32 + yy)*32 + xx];
                }
            }
        outp[HOFF*64 + idx] = fmaxf(acc, 0.f);
    }
}

// ---------------- merged matmul (f32x2) ----------------
template<int IN, int OUT, int RT>
__global__ void k_mmT(const float* __restrict__ Xm, const float* __restrict__ Xh,
                      const float* __restrict__ Wm, const float* __restrict__ Wh,
                      const float* __restrict__ bm, const float* __restrict__ bh,
                      float* __restrict__ Ym, float* __restrict__ Yh, int HB) {
    constexpr int nOG = OUT/4;
    constexpr int RB  = RT*(256/nOG);
    extern __shared__ float sm[];
    float* Ws = sm;
    float* Xs = sm + IN*OUT;
    int tid = threadIdx.x;
    const float *X, *WT, *bias; float* Y; size_t row0;
    if ((int)blockIdx.x < HB) { X=Xm; WT=Wm; bias=bm; Y=Ym; row0=(size_t)blockIdx.x*RB; }
    else { X=Xh; WT=Wh; bias=bh; Y=Yh; row0=(size_t)(blockIdx.x-HB)*RB; }
    for (int i = tid; i < OUT*IN/4; i += 256) ((float4*)Ws)[i] = ((const float4*)WT)[i];
    for (int i = tid; i < RB*IN/4; i += 256)
        ((float4*)Xs)[i] = ((const float4*)(X + row0*IN))[i];
    __syncthreads();
    int og = tid % nOG, rg = tid / nOG;
    float4 bv = bias ? *(const float4*)(bias + og*4) : make_float4(0.f,0.f,0.f,0.f);
    ull acc2[RT][2];
    #pragma unroll
    for (int r = 0; r < RT; r++) { acc2[r][0] = pk2(bv.x, bv.y); acc2[r][1] = pk2(bv.z, bv.w); }
    #pragma unroll 2
    for (int k = 0; k < IN; k += 4) {
        ulonglong2 w0 = *(const ulonglong2*)&Ws[(k+0)*OUT + og*4];
        ulonglong2 w1 = *(const ulonglong2*)&Ws[(k+1)*OUT + og*4];
        ulonglong2 w2 = *(const ulonglong2*)&Ws[(k+2)*OUT + og*4];
        ulonglong2 w3 = *(const ulonglong2*)&Ws[(k+3)*OUT + og*4];
        #pragma unroll
        for (int r = 0; r < RT; r++) {
            float4 av = *(const float4*)&Xs[(rg*RT + r)*IN + k];
            ull ax = pk2(av.x, av.x), ay = pk2(av.y, av.y);
            ull az = pk2(av.z, av.z), aw = pk2(av.w, av.w);
            acc2[r][0] = ff2(w0.x, ax, acc2[r][0]); acc2[r][1] = ff2(w0.y, ax, acc2[r][1]);
            acc2[r][0] = ff2(w1.x, ay, acc2[r][0]); acc2[r][1] = ff2(w1.y, ay, acc2[r][1]);
            acc2[r][0] = ff2(w2.x, az, acc2[r][0]); acc2[r][1] = ff2(w2.y, az, acc2[r][1]);
            acc2[r][0] = ff2(w3.x, aw, acc2[r][0]); acc2[r][1] = ff2(w3.y, aw, acc2[r][1]);
        }
    }
    #pragma unroll
    for (int r = 0; r < RT; r++) {
        float2 lo = up2(acc2[r][0]), hi = up2(acc2[r][1]);
        float4 o; o.x = lo.x; o.y = lo.y; o.z = hi.x; o.w = hi.y;
        *(float4*)&Y[(row0 + rg*RT + r)*OUT + og*4] = o;
    }
}

// ---------------- convproj ----------------
__global__ void k_convproj(const float* __restrict__ xz, const float* __restrict__ cwT,
        const float* __restrict__ convb, const float* __restrict__ WxpP,
        const float* __restrict__ WdtT, const float* __restrict__ bdt,
        float* __restrict__ u_out, float* __restrict__ dt_out, float* __restrict__ bc_out,
        int blkM, int blkH, int HB) {
    __shared__ float Wxps[4752], us[32*132], xds[32*40], Wdts[512], bdts[128], cws[512], cbs[128];
    int tid = threadIdx.x;
    int blk, g0, Lmask;
    if ((int)blockIdx.x < HB) { blk = blkM; g0 = blockIdx.x*32; Lmask = 16383; }
    else { blk = blkH; g0 = HOFF + (blockIdx.x - HB)*32; Lmask = 1023; }
    for (int i = tid; i < 4752; i += 256) Wxps[i] = WxpP[blk*4752 + i];
    for (int i = tid; i < 512; i += 256) { Wdts[i] = WdtT[blk*512 + i]; cws[i] = cwT[blk*512 + i]; }
    if (tid < 128) { bdts[tid] = bdt[blk*128 + tid]; cbs[tid] = convb[blk*128 + tid]; }
    __syncthreads();
    for (int i = tid; i < 1024; i += 256) {
        int tt = i >> 5, d4 = (i & 31)*4;
        int g = g0 + tt, t = g & Lmask;
        float4 acc = *(const float4*)&cbs[d4];
        #pragma unroll
        for (int j = 0; j < 4; j++) {
            if (t - 3 + j >= 0) {
                float4 xv = *(const float4*)&xz[(size_t)(g-3+j)*256 + d4];
                float4 wv = *(const float4*)&cws[j*128 + d4];
                acc.x += wv.x*xv.x; acc.y += wv.y*xv.y; acc.z += wv.z*xv.z; acc.w += wv.w*xv.w;
            }
        }
        float4 uu;
        uu.x = fsilu(acc.x); uu.y = fsilu(acc.y);
        uu.z = fsilu(acc.z); uu.w = fsilu(acc.w);
        *(float4*)&us[tt*132 + d4] = uu;
        *(float4*)&u_out[(size_t)g*128 + d4] = uu;
    }
    __syncthreads();
    for (int i = tid; i < 576; i += 256) {
        int tt = i & 31, op = i >> 5;
        int o0 = op*2;
        const float* up  = &us[tt*132];
        const float* w0p = &Wxps[o0*132];
        const float* w1p = &Wxps[o0*132 + 132];
        float a0 = 0.f, a1 = 0.f;
        #pragma unroll 4
        for (int k = 0; k < 128; k += 4) {
            float4 uv = *(const float4*)&up[k];
            float4 w0 = *(const float4*)&w0p[k];
            float4 w1 = *(const float4*)&w1p[k];
            a0 += w0.x*uv.x + w0.y*uv.y + w0.z*uv.z + w0.w*uv.w;
            a1 += w1.x*uv.x + w1.y*uv.y + w1.z*uv.z + w1.w*uv.w;
        }
        xds[tt*40 + o0] = a0; xds[tt*40 + o0 + 1] = a1;
    }
    __syncthreads();
    for (int i = tid; i < 1024; i += 256) {
        int tt = i >> 5;
        bc_out[(size_t)(g0+tt)*32 + (i & 31)] = xds[tt*40 + (i & 31) + 4];
    }
    for (int i = tid; i < 1024; i += 256) {
        int tt = i >> 5, d4 = (i & 31)*4;
        float4 dtp = *(const float4*)&bdts[d4];
        #pragma unroll
        for (int r = 0; r < 4; r++) {
            float x = xds[tt*40 + r];
            float4 wv = *(const float4*)&Wdts[r*128 + d4];
            dtp.x += x*wv.x; dtp.y += x*wv.y; dtp.z += x*wv.z; dtp.w += x*wv.w;
        }
        float4 o;
        o.x = fsoftplus(dtp.x); o.y = fsoftplus(dtp.y);
        o.z = fsoftplus(dtp.z); o.w = fsoftplus(dtp.w);
        *(float4*)&dt_out[(size_t)(g0+tt)*128 + d4] = o;
    }
}

// ---------------- scan ----------------
__device__ __forceinline__ bool load_A(const float* Alog, int d, float* An) {
    #pragma unroll
    for (int n = 0; n < 16; n++) An[n] = -__expf(Alog[d*16 + n]);
    bool geom = true;
    #pragma unroll
    for (int n = 1; n < 16; n++)
        if (fabsf(An[n] - (float)(n+1)*An[0]) > 1e-4f*(float)(n+1)) geom = false;
    return geom;
}

__global__ void k_scan1(const float* __restrict__ dt_a, const float* __restrict__ u_a,
                        const float* __restrict__ bc_a, const float* __restrict__ Alog,
                        float* __restrict__ hend, float* __restrict__ sdt_out,
                        int blkM, int blkH) {
    extern __shared__ float smS[];
    float* dtS = smS;
    float* uS  = smS + 64*128;
    float* bcS = smS + 64*256;
    int chunk = blockIdx.x;
    int d = threadIdx.x;
    const float* Al = Alog + ((chunk < 1024) ? blkM : blkH)*2048;
    size_t base = (size_t)chunk*64;
    const float4* dg = (const float4*)(dt_a + base*128);
    const float4* ug = (const float4*)(u_a + base*128);
    const float4* bg = (const float4*)(bc_a + base*32);
    for (int i = d; i < 64*32; i += 128) { ((float4*)dtS)[i] = dg[i]; ((float4*)uS)[i] = ug[i]; }
    for (int i = d; i < 64*8;  i += 128) ((float4*)bcS)[i] = bg[i];
    __syncthreads();
    float An[16];
    bool geom = load_A(Al, d, An);
    float h[16];
    #pragma unroll
    for (int n = 0; n < 16; n++) h[n] = 0.f;
    float s = 0.f;
    for (int tt = 0; tt < 64; tt++) {
        float dt = dtS[tt*128 + d];
        float du = dt * uS[tt*128 + d];
        s += dt;
        const float* Bv = &bcS[tt*32];
        if (geom) {
            float ep[16];
            ep[0] = __expf(dt * An[0]);
            #pragma unroll
            for (int n = 1; n < 16; n++) ep[n] = ep[(n-1)>>1]*ep[n>>1];
            #pragma unroll
            for (int n = 0; n < 16; n++) h[n] = ep[n]*h[n] + du*Bv[n];
        } else {
            #pragma unroll
            for (int n = 0; n < 16; n++) h[n] = __expf(dt*An[n])*h[n] + du*Bv[n];
        }
    }
    float* he = hend + ((size_t)chunk*128 + d)*16;
    #pragma unroll
    for (int n = 0; n < 16; n++) he[n] = h[n];
    sdt_out[chunk*128 + d] = s;
}

__global__ void k_carry(const float* __restrict__ hend, const float* __restrict__ sdt,
                        const float* __restrict__ Alog, float* __restrict__ hinit,
                        int blkM, int blkH) {
    int blk = blockIdx.x;
    int tid = threadIdx.x;
    int NC, chunk0, half; const float* Al;
    if (blk < 8) { NC = 256; chunk0 = (blk >> 1)*256; half = blk & 1; Al = Alog + blkM*2048; }
    else { int i = blk - 8; NC = 16; chunk0 = 1024 + (i >> 1)*16; half = i & 1; Al = Alog + blkH*2048; }
    int d = half*64 + (tid >> 4), n = tid & 15;
    float An = -__expf(Al[d*16 + n]);
    float h = 0.f;
    for (int c0 = 0; c0 < NC; c0 += 8) {
        float e8[8], v8[8];
        #pragma unroll
        for (int j = 0; j < 8; j++) {
            size_t off = (size_t)(chunk0 + c0 + j)*2048 + half*1024 + tid;
            v8[j] = hend[off];
            e8[j] = __expf(sdt[(chunk0 + c0 + j)*128 + d]*An);
        }
        #pragma unroll
        for (int j = 0; j < 8; j++) {
            size_t off = (size_t)(chunk0 + c0 + j)*2048 + half*1024 + tid;
            hinit[off] = h;
            h = e8[j]*h + v8[j];
        }
    }
}

__global__ void k_scan2(const float* __restrict__ dt_a, const float* __restrict__ u_a,
                        const float* __restrict__ bc_a, const float* __restrict__ Alog,
                        const float* __restrict__ hinit, const float* __restrict__ xz,
                        const float* __restrict__ Dp, float* __restrict__ yz,
                        int blkM, int blkH) {
    extern __shared__ float smS[];
    float* dtS = smS;
    float* uS  = smS + 64*128;
    float* bcS = smS + 64*256;
    int chunk = blockIdx.x;
    int d = threadIdx.x;
    int blk = (chunk < 1024) ? blkM : blkH;
    const float* Al = Alog + blk*2048;
    size_t base = (size_t)chunk*64;
    const float4* dg = (const float4*)(dt_a + base*128);
    const float4* ug = (const float4*)(u_a + base*128);
    const float4* bg = (const float4*)(bc_a + base*32);
    for (int i = d; i < 64*32; i += 128) { ((float4*)dtS)[i] = dg[i]; ((float4*)uS)[i] = ug[i]; }
    for (int i = d; i < 64*8;  i += 128) ((float4*)bcS)[i] = bg[i];
    __syncthreads();
    float An[16];
    bool geom = load_A(Al, d, An);
    float h[16];
    const float* hi = hinit + ((size_t)chunk*128 + d)*16;
    #pragma unroll
    for (int n = 0; n < 16; n++) h[n] = hi[n];
    float dcoef = Dp[blk*128 + d];
    for (int tt = 0; tt < 64; tt++) {
        size_t row = base + tt;
        float dt = dtS[tt*128 + d];
        float u  = uS[tt*128 + d];
        float du = dt * u;
        float y = 0.f;
        const float* Bv = &bcS[tt*32];
        if (geom) {
            float ep[16];
            ep[0] = __expf(dt * An[0]);
            #pragma unroll
            for (int n = 1; n < 16; n++) ep[n] = ep[(n-1)>>1]*ep[n>>1];
            #pragma unroll
            for (int n = 0; n < 16; n++) {
                h[n] = ep[n]*h[n] + du*Bv[n]; y += h[n]*Bv[16 + n];
            }
        } else {
            #pragma unroll
            for (int n = 0; n < 16; n++) {
                h[n] = __expf(dt*An[n])*h[n] + du*Bv[n]; y += h[n]*Bv[16 + n];
            }
        }
        float ys = y + u*dcoef;
        float z = xz[row*256 + 128 + d];
        yz[row*128 + d] = ys * fsilu(z);
    }
}

// ---------------- merged tiled transpose ----------------
__global__ void k_transp(const float* __restrict__ src, float* __restrict__ dstM,
                         float* __restrict__ dstH) {
    __shared__ float t[32][33];
    int bx = blockIdx.x;
    const float* s; float* dst; int P;
    if (bx < 512) { s = src; dst = dstM; P = 16384; }
    else { s = src + HOFF*64; dst = dstH; P = 1024; bx -= 512; }
    int p0 = bx*32, c0 = blockIdx.y*32, b = blockIdx.z;
    int tx = threadIdx.x, ty = threadIdx.y;
    #pragma unroll
    for (int i = ty; i < 32; i += 8)
        t[i][tx] = s[((size_t)b*64 + c0 + i)*P + p0 + tx];
    __syncthreads();
    #pragma unroll
    for (int i = ty; i < 32; i += 8)
        dst[((size_t)b*P + p0 + i)*64 + c0 + tx] = t[tx][i];
}

// ---------------- fused MLP tail (f32x2, weights streamed from L2) ----------------
#define TP_PS 17408
#define TP_TOT 17600

__global__ void k_tail(const float* __restrict__ F1, const float* __restrict__ G1,
                       const float* __restrict__ Wr_g, const float* __restrict__ b2g,
                       const float* __restrict__ W2Tg, const float* __restrict__ W3g,
                       const float* __restrict__ b3g, float* __restrict__ outp) {
    extern __shared__ float sm[];
    float* h1T = sm;
    float* h2  = sm;
    float* prs = sm + 8448;
    int*   frowS = (int*)(sm + TP_PS);
    float* relYS = sm + TP_PS + 64;
    float* relXS = sm + TP_PS + 128;
    int tid = threadIdx.x;
    float w0 = Wr_g[tid*2], w1 = Wr_g[tid*2 + 1];
    int jg = tid & 31, ig = tid >> 5;
    int j0 = jg*4, i0 = ig*8;
    float4 b2v = *(const float4*)(b2g + j0);
    float b3c = b3g[jg];

    for (int pp = 0; pp < 4; pp++) {
        int pixA = blockIdx.x*64 + pp*16;
        if (tid < 64) {
            int pl = tid >> 2, s = tid & 3;
            int pix = pixA + pl;
            int yy = (pix >> 7) & 127, xx = pix & 127, bb = pix >> 14;
            float sy = (s & 2) ? 0.5f : -0.5f;
            float sx = (s & 1) ? 0.5f : -0.5f;
            int iyr = __float2int_rn((float)(2*yy+1)*0.125f - 0.5f + sy);
            int ixr = __float2int_rn((float)(2*xx+1)*0.125f - 0.5f + sx);
            if (iyr >= 0 && iyr < 32 && ixr >= 0 && ixr < 32) {
                frowS[tid] = bb*1024 + iyr*32 + ixr;
                relYS[tid] = (float)(2*yy+1)*0.25f - (float)(2*iyr+1);
                relXS[tid] = (float)(2*xx+1)*0.25f - (float)(2*ixr+1);
            } else {
                frowS[tid] = -1;
                relYS[tid] = (float)(2*yy+1)*0.25f - 32.f;
                relXS[tid] = (float)(2*xx+1)*0.25f - 32.f;
            }
        }
        __syncthreads();
        for (int pl = 0; pl < 16; pl++) {
            float g = G1[(size_t)(pixA + pl)*256 + tid];
            float4 vv;
            #pragma unroll
            for (int s = 0; s < 4; s++) {
                int inst = pl*4 + s;
                int fr = frowS[inst];
                float fv = (fr >= 0) ? F1[(size_t)fr*256 + tid] : 0.f;
                float v = g + fv + w0*relYS[inst] + w1*relXS[inst];
                (&vv.x)[s] = fmaxf(v, 0.f);
            }
            *(float4*)&h1T[tid*68 + pl*4] = vv;
        }
        __syncthreads();
        ull acc2[8][2];
        #pragma unroll
        for (int r = 0; r < 8; r++) { acc2[r][0] = pk2(b2v.x, b2v.y); acc2[r][1] = pk2(b2v.z, b2v.w); }
        #pragma unroll 4
        for (int k = 0; k < 256; k++) {
            ulonglong2 wu = *(const ulonglong2*)&W2Tg[k*128 + j0];
            float ha[8];
            *(float4*)&ha[0] = *(const float4*)&h1T[k*68 + i0];
            *(float4*)&ha[4] = *(const float4*)&h1T[k*68 + i0 + 4];
            #pragma unroll
            for (int r = 0; r < 8; r++) {
                ull au = pk2(ha[r], ha[r]);
                acc2[r][0] = ff2(wu.x, au, acc2[r][0]);
                acc2[r][1] = ff2(wu.y, au, acc2[r][1]);
            }
        }
        __syncthreads();
        #pragma unroll
        for (int r = 0; r < 8; r++) {
            float2 lo = up2(acc2[r][0]), hi = up2(acc2[r][1]);
            float4 hv;
            hv.x = fmaxf(lo.x, 0.f); hv.y = fmaxf(lo.y, 0.f);
            hv.z = fmaxf(hi.x, 0.f); hv.w = fmaxf(hi.y, 0.f);
            *(float4*)&h2[(i0 + r)*132 + j0] = hv;
        }
        __syncthreads();
        {
            ull a2[8];
            #pragma unroll
            for (int r = 0; r < 8; r++) a2[r] = pk2(b3c, 0.f);
            const float* wrow = W3g + jg*128;
            #pragma unroll 4
            for (int k = 0; k < 128; k += 4) {
                ulonglong2 wu = *(const ulonglong2*)&wrow[k];
                #pragma unroll
                for (int r = 0; r < 8; r++) {
                    ulonglong2 hu = *(const ulonglong2*)&h2[(i0 + r)*132 + k];
                    a2[r] = ff2(wu.x, hu.x, a2[r]);
                    a2[r] = ff2(wu.y, hu.y, a2[r]);
                }
            }
            #pragma unroll
            for (int r = 0; r < 8; r++) {
                float2 p = up2(a2[r]);
                prs[(i0 + r)*36 + jg] = p.x + p.y;
            }
        }
        __syncthreads();
        for (int i = tid; i < 496; i += 256) {
            int pl = i / 31, c = i % 31;
            int base = pl*4;
            float l0 = prs[(base+0)*36 + 31];
            float l1 = prs[(base+1)*36 + 31];
            float l2 = prs[(base+2)*36 + 31];
            float l3 = prs[(base+3)*36 + 31];
            float m = fmaxf(fmaxf(l0, l1), fmaxf(l2, l3));
            float e0 = __expf(l0 - m), e1 = __expf(l1 - m);
            float e2 = __expf(l2 - m), e3 = __expf(l3 - m);
            float inv = __fdividef(1.f, e0 + e1 + e2 + e3);
            float v = (prs[(base+0)*36 + c]*e0 + prs[(base+1)*36 + c]*e1
                     + prs[(base+2)*36 + c]*e2 + prs[(base+3)*36 + c]*e3) * inv;
            int pix = pixA + pl;
            int bb = pix >> 14, yy = (pix >> 7) & 127, xx = pix & 127;
            outp[((size_t)bb*31 + c)*16384 + yy*128 + xx] = v;
        }
        __syncthreads();
    }
}

// ---------------- host ----------------
#define SMM_A ((64*256 + 32*64)*4)
#define SMM_B ((128*64 + 128*128)*4)
#define SSC64 ((64*256 + 64*32)*4)

extern "C" void kernel_launch(void* const* d_in, const int* in_sizes, int n_in,
                              void* d_out, int out_size) {
    const float* hsi  = (const float*)d_in[0];
    const float* msi  = (const float*)d_in[1];
    const float* ehw  = (const float*)d_in[2];
    const float* ehb  = (const float*)d_in[3];
    const float* emw  = (const float*)d_in[4];
    const float* emb  = (const float*)d_in[5];
    const float* Win  = (const float*)d_in[6];
    const float* convw= (const float*)d_in[7];
    const float* convb= (const float*)d_in[8];
    const float* Wxp  = (const float*)d_in[9];
    const float* Wdt  = (const float*)d_in[10];
    const float* bdt  = (const float*)d_in[11];
    const float* Alog = (const float*)d_in[12];
    const float* Dp   = (const float*)d_in[13];
    const float* Wout = (const float*)d_in[14];
    const float* W1   = (const float*)d_in[15];
    const float* b1   = (const float*)d_in[16];
    const float* W2   = (const float*)d_in[17];
    const float* b2   = (const float*)d_in[18];
    const float* W3   = (const float*)d_in[19];
    const float* b3   = (const float*)d_in[20];
    float* outp = (float*)d_out;

    float *tokA, *tokB, *xz, *u, *dt, *bc, *yz, *hend, *hinit, *sdt, *featT, *guideT, *F1, *G1;
    float *WinT, *WoutT, *W1fT, *W1gT, *Wr, *W2T, *WxpP, *WdtT, *cwT;
    cudaGetSymbolAddress((void**)&tokA, g_tokA);
    cudaGetSymbolAddress((void**)&tokB, g_tokB);
    cudaGetSymbolAddress((void**)&xz, g_xz);
    cudaGetSymbolAddress((void**)&u, g_u);
    cudaGetSymbolAddress((void**)&dt, g_dt);
    cudaGetSymbolAddress((void**)&bc, g_bc);
    cudaGetSymbolAddress((void**)&yz, g_yz);
    cudaGetSymbolAddress((void**)&hend, g_hend);
    cudaGetSymbolAddress((void**)&hinit, g_hinit);
    cudaGetSymbolAddress((void**)&sdt, g_sdt);
    cudaGetSymbolAddress((void**)&featT, g_featT);
    cudaGetSymbolAddress((void**)&guideT, g_guideT);
    cudaGetSymbolAddress((void**)&F1, g_F1);
    cudaGetSymbolAddress((void**)&G1, g_G1);
    cudaGetSymbolAddress((void**)&WinT, g_WinT);
    cudaGetSymbolAddress((void**)&WoutT, g_WoutT);
    cudaGetSymbolAddress((void**)&W1fT, g_W1fT);
    cudaGetSymbolAddress((void**)&W1gT, g_W1gT);
    cudaGetSymbolAddress((void**)&Wr, g_Wr);
    cudaGetSymbolAddress((void**)&W2T, g_W2T);
    cudaGetSymbolAddress((void**)&WxpP, g_WxpP);
    cudaGetSymbolAddress((void**)&WdtT, g_WdtT);
    cudaGetSymbolAddress((void**)&cwT, g_cwT);

    cudaFuncSetAttribute(k_mmT<64,256,8>, cudaFuncAttributeMaxDynamicSharedMemorySize, SMM_A);
    cudaFuncSetAttribute(k_mmT<128,64,8>, cudaFuncAttributeMaxDynamicSharedMemorySize, SMM_B);
    cudaFuncSetAttribute(k_scan1, cudaFuncAttributeMaxDynamicSharedMemorySize, SSC64);
    cudaFuncSetAttribute(k_scan2, cudaFuncAttributeMaxDynamicSharedMemorySize, SSC64);
    cudaFuncSetAttribute(k_tail, cudaFuncAttributeMaxDynamicSharedMemorySize, TP_TOT*4);

    k_prep<<<730, 256>>>(Win, Wout, W1, W2, Wxp, Wdt, convw,
                         WinT, WoutT, W1fT, W1gT, Wr, W2T, WxpP, WdtT, cwT);

    k_conv<<<17408, 256>>>(msi, hsi, emw, emb, ehw, ehb, tokA);

    const float* src = tokA;
    float* dst = tokB;
    int blks[2][2] = {{2, 0}, {3, 1}};
    for (int st = 0; st < 2; st++) {
        int bM = blks[st][0], bH = blks[st][1];
        k_mmT<64,256,8><<<2176, 256, SMM_A>>>(src, src + HOFF*64,
            WinT + bM*16384, WinT + bH*16384, nullptr, nullptr,
            xz, xz + (size_t)HOFF*256, 2048);
        k_convproj<<<2176, 256>>>(xz, cwT, convb, WxpP, WdtT, bdt,
                                  u, dt, bc, bM, bH, 2048);
        k_scan1<<<1088, 128, SSC64>>>(dt, u, bc, Alog, hend, sdt, bM, bH);
        k_carry<<<16, 1024>>>(hend, sdt, Alog, hinit, bM, bH);
        k_scan2<<<1088, 128, SSC64>>>(dt, u, bc, Alog, hinit, xz, Dp, yz, bM, bH);
        k_mmT<128,64,8><<<544, 256, SMM_B>>>(yz, yz + (size_t)HOFF*128,
            WoutT + bM*8192, WoutT + bH*8192, nullptr, nullptr,
            dst, dst + HOFF*64, 512);
        const float* t2 = dst; dst = (float*)src; src = t2;
    }
    { dim3 g(544, 2, 4), blkd(32, 8); k_transp<<<g, blkd>>>(src, guideT, featT); }

    k_mmT<64,256,8><<<2176, 256, SMM_A>>>(guideT, featT, W1gT, W1fT, b1, nullptr, G1, F1, 2048);
    k_tail<<<1024, 256, TP_TOT*4>>>(F1, G1, Wr, b2, W2T, W3, b3, outp);
}